// round 1
// baseline (speedup 1.0000x reference)
#include <cuda_runtime.h>
#include <math.h>

#define HH 256
#define WW_ 256
#define CC 64
#define WIN 8
#define PP 64
#define SHIFT 4

// Precomputed normalized q: (B=8, C=64, P=64)
__device__ float g_qn[8 * 64 * 64];

__global__ void qn_kernel(const float* __restrict__ q) {
    int row = blockIdx.x * blockDim.x + threadIdx.x;  // 0..511 = b*64+c
    if (row >= 8 * 64) return;
    const float* qr = q + row * 64;
    float ss = 0.f;
#pragma unroll
    for (int p = 0; p < 64; p++) { float v = qr[p]; ss += v * v; }
    float inv = 1.f / fmaxf(sqrtf(ss), 1e-12f);
#pragma unroll
    for (int p = 0; p < 64; p++) g_qn[row * 64 + p] = qr[p] * inv;
}

// One CTA per window (8192 CTAs). 256 threads.
// Dynamic smem layout (floats, rows padded to 65 to avoid bank conflicts):
//   A  : 64*65   scratch (xw, then scores S)
//   Bt : 128*65  conv1x1 output t; first 64*65 reused as O accumulator
//   K  : 64*65   kn   (kv_w staged in K..V span before dwconv)
//   V  : 64*65   v
//   Q  : 64*65   qn
__global__ __launch_bounds__(256) void win_kernel(
    const float* __restrict__ x,
    const float* __restrict__ kv_w,
    const float* __restrict__ dw_w,
    const float* __restrict__ proj_w,
    const float* __restrict__ rs1,
    const float* __restrict__ rs2,
    float* __restrict__ out)
{
    extern __shared__ float sm[];
    float* A  = sm;                    // 4160
    float* Bt = sm + 4160;             // 8320
    float* K  = sm + 4160 + 8320;      // 4160
    float* V  = K + 4160;              // 4160
    float* Q  = V + 4160;              // 4160
    float* W2 = K;                     // 8192-float staging span (K..V)

    const int tid = threadIdx.x;
    const int ty = tid >> 4, tx = tid & 15;
    const int r0 = ty * 4, c0 = tx * 4;
    const int wid = tid >> 5, lane = tid & 31;

    const int bw = blockIdx.x;
    const int b  = bw >> 10;           // 1024 windows per batch
    const int w  = bw & 1023;
    const int wh = w >> 5, ww = w & 31;

    const float r1v = rs1[0];
    const float r2v = rs2[0];

    // ---- Load window of x (roll -4 folded in), qn, and stage kv_w ----
    const float* xb = x + (size_t)b * CC * HH * WW_;
    for (int idx = tid; idx < 4096; idx += 256) {
        int c = idx >> 6, p = idx & 63;
        int i = p >> 3, j = p & 7;
        int gh = (wh * 8 + i + SHIFT) & 255;
        int gw = (ww * 8 + j + SHIFT) & 255;
        A[c * 65 + p] = xb[(size_t)c * HH * WW_ + gh * WW_ + gw];
        Q[c * 65 + p] = g_qn[(b * 64 + c) * 64 + p];
    }
    for (int idx = tid; idx < 8192; idx += 256) W2[idx] = kv_w[idx];
    __syncthreads();

    // ---- conv1x1: t[oc][p] = sum_c kv_w[oc][c] * xw[c][p]  (128x64) ----
    {
        float acc[8][4];
#pragma unroll
        for (int r = 0; r < 8; r++)
#pragma unroll
            for (int cc = 0; cc < 4; cc++) acc[r][cc] = 0.f;
        const int ocb = ty * 8;
#pragma unroll 4
        for (int k = 0; k < 64; k++) {
            float xv[4];
#pragma unroll
            for (int cc = 0; cc < 4; cc++) xv[cc] = A[k * 65 + c0 + cc];
#pragma unroll
            for (int r = 0; r < 8; r++) {
                float wv = W2[(ocb + r) * 64 + k];
#pragma unroll
                for (int cc = 0; cc < 4; cc++)
                    acc[r][cc] = fmaf(wv, xv[cc], acc[r][cc]);
            }
        }
        __syncthreads();   // everyone done reading W2 (and A) before overwrite
#pragma unroll
        for (int r = 0; r < 8; r++)
#pragma unroll
            for (int cc = 0; cc < 4; cc++)
                Bt[(ocb + r) * 65 + c0 + cc] = acc[r][cc];
        __syncthreads();
    }

    // ---- depthwise 3x3 (zero pad) -> K (oc<64), V (oc>=64) ----
    for (int idx = tid; idx < 8192; idx += 256) {
        int oc = idx >> 6, p = idx & 63;
        int i = p >> 3, j = p & 7;
        const float* wp = dw_w + oc * 9;
        float s = 0.f;
#pragma unroll
        for (int dy = -1; dy <= 1; dy++) {
            int ii = i + dy;
            if (ii < 0 || ii > 7) continue;
#pragma unroll
            for (int dx = -1; dx <= 1; dx++) {
                int jj = j + dx;
                if (jj < 0 || jj > 7) continue;
                s = fmaf(wp[(dy + 1) * 3 + (dx + 1)], Bt[oc * 65 + ii * 8 + jj], s);
            }
        }
        if (oc < 64) K[oc * 65 + p] = s;
        else         V[(oc - 64) * 65 + p] = s;
    }
    __syncthreads();

    // ---- l2norm rows of K ----
    for (int r = wid; r < 64; r += 8) {
        float v0 = K[r * 65 + lane], v1 = K[r * 65 + 32 + lane];
        float ss = v0 * v0 + v1 * v1;
#pragma unroll
        for (int o = 16; o; o >>= 1) ss += __shfl_xor_sync(0xffffffffu, ss, o);
        float inv = 1.f / fmaxf(sqrtf(ss), 1e-12f);
        K[r * 65 + lane] = v0 * inv;
        K[r * 65 + 32 + lane] = v1 * inv;
    }
    __syncthreads();

    // ---- S1 = (K @ Q^T) * r1 -> A ----
    {
        float a[4][4] = {};
#pragma unroll 4
        for (int k = 0; k < 64; k++) {
            float av[4], bv[4];
#pragma unroll
            for (int i = 0; i < 4; i++) av[i] = K[(r0 + i) * 65 + k];
#pragma unroll
            for (int j = 0; j < 4; j++) bv[j] = Q[(c0 + j) * 65 + k];
#pragma unroll
            for (int i = 0; i < 4; i++)
#pragma unroll
                for (int j = 0; j < 4; j++) a[i][j] = fmaf(av[i], bv[j], a[i][j]);
        }
#pragma unroll
        for (int i = 0; i < 4; i++)
#pragma unroll
            for (int j = 0; j < 4; j++) A[(r0 + i) * 65 + c0 + j] = a[i][j] * r1v;
    }
    __syncthreads();

    // ---- row softmax of A ----
    for (int r = wid; r < 64; r += 8) {
        float v0 = A[r * 65 + lane], v1 = A[r * 65 + 32 + lane];
        float m = fmaxf(v0, v1);
#pragma unroll
        for (int o = 16; o; o >>= 1) m = fmaxf(m, __shfl_xor_sync(0xffffffffu, m, o));
        float e0 = __expf(v0 - m), e1 = __expf(v1 - m);
        float s = e0 + e1;
#pragma unroll
        for (int o = 16; o; o >>= 1) s += __shfl_xor_sync(0xffffffffu, s, o);
        float inv = 1.f / s;
        A[r * 65 + lane] = e0 * inv;
        A[r * 65 + 32 + lane] = e1 * inv;
    }
    __syncthreads();

    // ---- out1 = A @ V -> O (reuse first half of Bt) ----
    float* O = Bt;
    {
        float a[4][4] = {};
#pragma unroll 4
        for (int k = 0; k < 64; k++) {
            float av[4], bv[4];
#pragma unroll
            for (int i = 0; i < 4; i++) av[i] = A[(r0 + i) * 65 + k];
#pragma unroll
            for (int j = 0; j < 4; j++) bv[j] = V[k * 65 + c0 + j];
#pragma unroll
            for (int i = 0; i < 4; i++)
#pragma unroll
                for (int j = 0; j < 4; j++) a[i][j] = fmaf(av[i], bv[j], a[i][j]);
        }
#pragma unroll
        for (int i = 0; i < 4; i++)
#pragma unroll
            for (int j = 0; j < 4; j++) O[(r0 + i) * 65 + c0 + j] = a[i][j];
    }
    __syncthreads();

    // ---- S2 = (K @ V^T) * r2 -> A ----
    {
        float a[4][4] = {};
#pragma unroll 4
        for (int k = 0; k < 64; k++) {
            float av[4], bv[4];
#pragma unroll
            for (int i = 0; i < 4; i++) av[i] = K[(r0 + i) * 65 + k];
#pragma unroll
            for (int j = 0; j < 4; j++) bv[j] = V[(c0 + j) * 65 + k];
#pragma unroll
            for (int i = 0; i < 4; i++)
#pragma unroll
                for (int j = 0; j < 4; j++) a[i][j] = fmaf(av[i], bv[j], a[i][j]);
        }
#pragma unroll
        for (int i = 0; i < 4; i++)
#pragma unroll
            for (int j = 0; j < 4; j++) A[(r0 + i) * 65 + c0 + j] = a[i][j] * r2v;
    }
    __syncthreads();

    // ---- row softmax of A ----
    for (int r = wid; r < 64; r += 8) {
        float v0 = A[r * 65 + lane], v1 = A[r * 65 + 32 + lane];
        float m = fmaxf(v0, v1);
#pragma unroll
        for (int o = 16; o; o >>= 1) m = fmaxf(m, __shfl_xor_sync(0xffffffffu, m, o));
        float e0 = __expf(v0 - m), e1 = __expf(v1 - m);
        float s = e0 + e1;
#pragma unroll
        for (int o = 16; o; o >>= 1) s += __shfl_xor_sync(0xffffffffu, s, o);
        float inv = 1.f / s;
        A[r * 65 + lane] = e0 * inv;
        A[r * 65 + 32 + lane] = e1 * inv;
    }
    __syncthreads();

    // ---- out2 = A @ Q, accumulate into O ----
    {
        float a[4][4] = {};
#pragma unroll 4
        for (int k = 0; k < 64; k++) {
            float av[4], bv[4];
#pragma unroll
            for (int i = 0; i < 4; i++) av[i] = A[(r0 + i) * 65 + k];
#pragma unroll
            for (int j = 0; j < 4; j++) bv[j] = Q[k * 65 + c0 + j];
#pragma unroll
            for (int i = 0; i < 4; i++)
#pragma unroll
                for (int j = 0; j < 4; j++) a[i][j] = fmaf(av[i], bv[j], a[i][j]);
        }
#pragma unroll
        for (int i = 0; i < 4; i++)
#pragma unroll
            for (int j = 0; j < 4; j++) O[(r0 + i) * 65 + c0 + j] += a[i][j];
    }
    __syncthreads();

    // ---- proj: y[oc][p] = sum_c proj_w[oc][c] * O[c][p]; store with roll +4 ----
    {
        float a[4][4] = {};
#pragma unroll 4
        for (int k = 0; k < 64; k++) {
            float wv[4], ov[4];
#pragma unroll
            for (int i = 0; i < 4; i++) wv[i] = __ldg(&proj_w[(r0 + i) * 64 + k]);
#pragma unroll
            for (int j = 0; j < 4; j++) ov[j] = O[k * 65 + c0 + j];
#pragma unroll
            for (int i = 0; i < 4; i++)
#pragma unroll
                for (int j = 0; j < 4; j++) a[i][j] = fmaf(wv[i], ov[j], a[i][j]);
        }
        float* ob = out + (size_t)b * CC * HH * WW_;
#pragma unroll
        for (int i = 0; i < 4; i++) {
            int oc = r0 + i;
#pragma unroll
            for (int j = 0; j < 4; j++) {
                int p = c0 + j;
                int pi = p >> 3, pj = p & 7;
                int gh = (wh * 8 + pi + SHIFT) & 255;
                int gw = (ww * 8 + pj + SHIFT) & 255;
                ob[(size_t)oc * HH * WW_ + gh * WW_ + gw] = a[i][j];
            }
        }
    }
}

extern "C" void kernel_launch(void* const* d_in, const int* in_sizes, int n_in,
                              void* d_out, int out_size) {
    const float* x      = (const float*)d_in[0];
    const float* q      = (const float*)d_in[1];
    const float* kv_w   = (const float*)d_in[2];
    const float* dw_w   = (const float*)d_in[3];
    const float* proj_w = (const float*)d_in[4];
    const float* rs1    = (const float*)d_in[5];
    const float* rs2    = (const float*)d_in[6];
    float* out = (float*)d_out;

    static bool attr_set = false;
    const int smem_bytes = 24960 * 4;  // 99,840 B
    if (!attr_set) {
        cudaFuncSetAttribute(win_kernel,
                             cudaFuncAttributeMaxDynamicSharedMemorySize,
                             smem_bytes);
        attr_set = true;
    }

    qn_kernel<<<2, 256>>>(q);
    win_kernel<<<8192, 256, smem_bytes>>>(x, kv_w, dw_w, proj_w, rs1, rs2, out);
}

// round 2
// speedup vs baseline: 1.5671x; 1.5671x over previous
#include <cuda_runtime.h>
#include <math.h>

#define HH 256
#define WW_ 256
#define SHIFT 4

// Precomputed normalized q: (B=8, C=64, P=64)
__device__ float g_qn[8 * 64 * 64];

__global__ void qn_kernel(const float* __restrict__ q) {
    int row = blockIdx.x * blockDim.x + threadIdx.x;  // 0..511 = b*64+c
    if (row >= 8 * 64) return;
    const float* qr = q + row * 64;
    float ss = 0.f;
#pragma unroll
    for (int p = 0; p < 64; p++) { float v = qr[p]; ss += v * v; }
    float inv = 1.f / fmaxf(sqrtf(ss), 1e-12f);
#pragma unroll
    for (int p = 0; p < 64; p++) g_qn[row * 64 + p] = qr[p] * inv;
}

// ---- tf32 helpers ----
__device__ __forceinline__ void split_tf32(float x, unsigned& hi, unsigned& lo) {
    unsigned h;
    asm("cvt.rna.tf32.f32 %0, %1;" : "=r"(h) : "f"(x));
    hi = h;
    lo = __float_as_uint(x - __uint_as_float(h));
}

__device__ __forceinline__ void mma8(float (&d)[4], const unsigned a[4], const unsigned b[2]) {
    asm("mma.sync.aligned.m16n8k8.row.col.f32.tf32.tf32.f32 "
        "{%0,%1,%2,%3}, {%4,%5,%6,%7}, {%8,%9}, {%0,%1,%2,%3};"
        : "+f"(d[0]), "+f"(d[1]), "+f"(d[2]), "+f"(d[3])
        : "r"(a[0]), "r"(a[1]), "r"(a[2]), "r"(a[3]), "r"(b[0]), "r"(b[1]));
}

// Generic warp GEMM: D(m,n) = sum_k A[m*lda+k] * B[k*bk + n*bn], 3xTF32.
// Warp computes rows [m0, m0+16), cols [n0, n0+8*NT). K = 64.
template <int NT, class Epi>
__device__ __forceinline__ void mma_gemm(
    const float* __restrict__ A, int lda,
    const float* __restrict__ B, int bk, int bn,
    int m0, int n0, int g, int t,
    const float* __restrict__ initD, int ldd, Epi epi)
{
    float acc[NT][4];
#pragma unroll
    for (int nt = 0; nt < NT; nt++) {
        if (initD) {
            int c = n0 + nt * 8 + 2 * t;
            acc[nt][0] = initD[(m0 + g) * ldd + c];
            acc[nt][1] = initD[(m0 + g) * ldd + c + 1];
            acc[nt][2] = initD[(m0 + g + 8) * ldd + c];
            acc[nt][3] = initD[(m0 + g + 8) * ldd + c + 1];
        } else {
            acc[nt][0] = acc[nt][1] = acc[nt][2] = acc[nt][3] = 0.f;
        }
    }
#pragma unroll
    for (int k0 = 0; k0 < 64; k0 += 8) {
        unsigned ah[4], al[4];
        split_tf32(A[(m0 + g) * lda + k0 + t],         ah[0], al[0]);
        split_tf32(A[(m0 + g + 8) * lda + k0 + t],     ah[1], al[1]);
        split_tf32(A[(m0 + g) * lda + k0 + t + 4],     ah[2], al[2]);
        split_tf32(A[(m0 + g + 8) * lda + k0 + t + 4], ah[3], al[3]);
#pragma unroll
        for (int nt = 0; nt < NT; nt++) {
            int n = n0 + nt * 8 + g;
            unsigned bh[2], bl[2];
            split_tf32(B[(k0 + t) * bk + n * bn],     bh[0], bl[0]);
            split_tf32(B[(k0 + t + 4) * bk + n * bn], bh[1], bl[1]);
            mma8(acc[nt], al, bh);
            mma8(acc[nt], ah, bl);
            mma8(acc[nt], ah, bh);
        }
    }
#pragma unroll
    for (int nt = 0; nt < NT; nt++) {
        int c = n0 + nt * 8 + 2 * t;
        epi(m0 + g,     c,     acc[nt][0]);
        epi(m0 + g,     c + 1, acc[nt][1]);
        epi(m0 + g + 8, c,     acc[nt][2]);
        epi(m0 + g + 8, c + 1, acc[nt][3]);
    }
}

// One CTA per window (8192 CTAs), 256 threads (8 warps).
// smem floats:
//   XS 0      : 4608  (X window, stride 72 -> then scores S, stride 68)
//   T  4608   : 9216  (conv t, stride 72; first 64 rows reused as O)
//   KB 13824  : 4352  (kn, stride 68; also kv_w staging [spans KB+V], proj_w staging)
//   V  18176  : 4608  (v, stride 72)
//   Q  22784  : 4352  (qn, stride 68)
// total 27136 floats = 108544 B
__global__ __launch_bounds__(256, 2) void win_kernel(
    const float* __restrict__ x,
    const float* __restrict__ kv_w,
    const float* __restrict__ dw_w,
    const float* __restrict__ proj_w,
    const float* __restrict__ rs1,
    const float* __restrict__ rs2,
    float* __restrict__ out)
{
    extern __shared__ float sm[];
    float* XS = sm;
    float* T  = sm + 4608;
    float* KB = sm + 13824;
    float* V  = sm + 18176;
    float* Q  = sm + 22784;

    const int tid  = threadIdx.x;
    const int wid  = tid >> 5;
    const int lane = tid & 31;
    const int g = lane >> 2, t = lane & 3;

    const int bw = blockIdx.x;
    const int b  = bw >> 10;
    const int w  = bw & 1023;
    const int wh = w >> 5, ww = w & 31;

    const float r1v = rs1[0];
    const float r2v = rs2[0];

    // ---- Phase 0: load X window (roll -4), qn, stage kv_w (stride 68) ----
    const float* xb = x + (size_t)b * 64 * HH * WW_;
    for (int idx = tid; idx < 4096; idx += 256) {
        int c = idx >> 6, p = idx & 63;
        int i = p >> 3, j = p & 7;
        int gh = (wh * 8 + i + SHIFT) & 255;
        int gw = (ww * 8 + j + SHIFT) & 255;
        XS[c * 72 + p] = xb[(size_t)c * HH * WW_ + gh * WW_ + gw];
        Q[c * 68 + p]  = g_qn[(b * 64 + c) * 64 + p];
    }
    for (int idx = tid; idx < 8192; idx += 256)
        KB[(idx >> 6) * 68 + (idx & 63)] = kv_w[idx];   // W2 staged over KB..V span
    __syncthreads();

    // ---- conv1x1: t(128x64) = W2 @ X ----
    mma_gemm<8>(KB, 68, XS, 72, 1, wid * 16, 0, g, t, (const float*)nullptr, 0,
        [&](int r, int c, float v) { T[r * 72 + c] = v; });
    __syncthreads();

    // ---- depthwise 3x3 (zero pad) -> KB (oc<64), V (oc>=64) ----
    for (int task = tid; task < 1024; task += 256) {
        int oc = task >> 3, i = task & 7;
        const float* trow = T + oc * 72;
        float r[3][8];
#pragma unroll
        for (int dy = 0; dy < 3; dy++) {
            int ii = i + dy - 1;
            if (ii < 0 || ii > 7) {
#pragma unroll
                for (int j = 0; j < 8; j++) r[dy][j] = 0.f;
            } else {
                float4 v0 = *(const float4*)(trow + ii * 8);
                float4 v1 = *(const float4*)(trow + ii * 8 + 4);
                r[dy][0] = v0.x; r[dy][1] = v0.y; r[dy][2] = v0.z; r[dy][3] = v0.w;
                r[dy][4] = v1.x; r[dy][5] = v1.y; r[dy][6] = v1.z; r[dy][7] = v1.w;
            }
        }
        float wv[9];
#pragma unroll
        for (int q = 0; q < 9; q++) wv[q] = __ldg(&dw_w[oc * 9 + q]);
        float o[8];
#pragma unroll
        for (int j = 0; j < 8; j++) {
            float s = 0.f;
#pragma unroll
            for (int dy = 0; dy < 3; dy++)
#pragma unroll
                for (int dx = 0; dx < 3; dx++) {
                    int jj = j + dx - 1;
                    if (jj < 0 || jj > 7) continue;
                    s = fmaf(wv[dy * 3 + dx], r[dy][jj], s);
                }
            o[j] = s;
        }
        float* dst = (oc < 64) ? (KB + oc * 68 + i * 8) : (V + (oc - 64) * 72 + i * 8);
        *(float4*)dst       = make_float4(o[0], o[1], o[2], o[3]);
        *(float4*)(dst + 4) = make_float4(o[4], o[5], o[6], o[7]);
    }
    __syncthreads();

    // ---- l2norm rows of K ----
    for (int r = wid; r < 64; r += 8) {
        float v0 = KB[r * 68 + lane], v1 = KB[r * 68 + 32 + lane];
        float ss = v0 * v0 + v1 * v1;
#pragma unroll
        for (int o = 16; o; o >>= 1) ss += __shfl_xor_sync(0xffffffffu, ss, o);
        float inv = 1.f / fmaxf(sqrtf(ss), 1e-12f);
        KB[r * 68 + lane] = v0 * inv;
        KB[r * 68 + 32 + lane] = v1 * inv;
    }
    __syncthreads();

    const int am0 = (wid & 3) * 16;
    const int an0 = (wid >> 2) * 32;

    // ---- S1 = (kn @ qn^T) * r1 -> XS (stride 68) ----
    mma_gemm<4>(KB, 68, Q, 1, 68, am0, an0, g, t, (const float*)nullptr, 0,
        [&](int r, int c, float v) { XS[r * 68 + c] = v * r1v; });
    __syncthreads();

    // ---- row softmax ----
    for (int r = wid; r < 64; r += 8) {
        float v0 = XS[r * 68 + lane], v1 = XS[r * 68 + 32 + lane];
        float m = fmaxf(v0, v1);
#pragma unroll
        for (int o = 16; o; o >>= 1) m = fmaxf(m, __shfl_xor_sync(0xffffffffu, m, o));
        float e0 = __expf(v0 - m), e1 = __expf(v1 - m);
        float s = e0 + e1;
#pragma unroll
        for (int o = 16; o; o >>= 1) s += __shfl_xor_sync(0xffffffffu, s, o);
        float inv = 1.f / s;
        XS[r * 68 + lane] = e0 * inv;
        XS[r * 68 + 32 + lane] = e1 * inv;
    }
    __syncthreads();

    // ---- out1 = A1 @ V -> O (=T, stride 72) ----
    mma_gemm<4>(XS, 68, V, 72, 1, am0, an0, g, t, (const float*)nullptr, 0,
        [&](int r, int c, float v) { T[r * 72 + c] = v; });
    __syncthreads();

    // ---- S2 = (kn @ v^T) * r2 -> XS ----
    mma_gemm<4>(KB, 68, V, 1, 72, am0, an0, g, t, (const float*)nullptr, 0,
        [&](int r, int c, float v) { XS[r * 68 + c] = v * r2v; });
    __syncthreads();

    // ---- row softmax + stage proj_w into KB (K no longer needed) ----
    for (int r = wid; r < 64; r += 8) {
        float v0 = XS[r * 68 + lane], v1 = XS[r * 68 + 32 + lane];
        float m = fmaxf(v0, v1);
#pragma unroll
        for (int o = 16; o; o >>= 1) m = fmaxf(m, __shfl_xor_sync(0xffffffffu, m, o));
        float e0 = __expf(v0 - m), e1 = __expf(v1 - m);
        float s = e0 + e1;
#pragma unroll
        for (int o = 16; o; o >>= 1) s += __shfl_xor_sync(0xffffffffu, s, o);
        float inv = 1.f / s;
        XS[r * 68 + lane] = e0 * inv;
        XS[r * 68 + 32 + lane] = e1 * inv;
    }
    for (int idx = tid; idx < 4096; idx += 256)
        KB[(idx >> 6) * 68 + (idx & 63)] = proj_w[idx];
    __syncthreads();

    // ---- out2 = A2 @ qn, accumulated into O(=T) ----
    mma_gemm<4>(XS, 68, Q, 68, 1, am0, an0, g, t, (const float*)T, 72,
        [&](int r, int c, float v) { T[r * 72 + c] = v; });
    __syncthreads();

    // ---- proj: y = PW @ O, store to gmem with roll +4 ----
    float* ob = out + (size_t)b * 64 * HH * WW_;
    mma_gemm<4>(KB, 68, T, 72, 1, am0, an0, g, t, (const float*)nullptr, 0,
        [&](int r, int c, float v) {
            int pi = c >> 3, pj = c & 7;
            int gh = (wh * 8 + pi + SHIFT) & 255;
            int gw = (ww * 8 + pj + SHIFT) & 255;
            ob[(size_t)r * HH * WW_ + gh * WW_ + gw] = v;
        });
}

extern "C" void kernel_launch(void* const* d_in, const int* in_sizes, int n_in,
                              void* d_out, int out_size) {
    const float* x      = (const float*)d_in[0];
    const float* q      = (const float*)d_in[1];
    const float* kv_w   = (const float*)d_in[2];
    const float* dw_w   = (const float*)d_in[3];
    const float* proj_w = (const float*)d_in[4];
    const float* rs1    = (const float*)d_in[5];
    const float* rs2    = (const float*)d_in[6];
    float* out = (float*)d_out;

    static bool attr_set = false;
    const int smem_bytes = 27136 * 4;  // 108,544 B
    if (!attr_set) {
        cudaFuncSetAttribute(win_kernel,
                             cudaFuncAttributeMaxDynamicSharedMemorySize,
                             smem_bytes);
        attr_set = true;
    }

    qn_kernel<<<2, 256>>>(q);
    win_kernel<<<8192, 256, smem_bytes>>>(x, kv_w, dw_w, proj_w, rs1, rs2, out);
}

// round 3
// speedup vs baseline: 1.6615x; 1.0602x over previous
#include <cuda_runtime.h>
#include <math.h>

#define HH 256
#define WW_ 256
#define SHIFT 4

// Pre-split constant operands: uint2 = (tf32 hi bits, fp32 residual bits)
__device__ uint2 g_w2[128 * 64];
__device__ uint2 g_pw[64 * 64];
__device__ uint2 g_q[8 * 64 * 64];   // normalized q, per batch

__device__ __forceinline__ uint2 split2(float x) {
    unsigned h;
    asm("cvt.rna.tf32.f32 %0, %1;" : "=r"(h) : "f"(x));
    return make_uint2(h, __float_as_uint(x - __uint_as_float(h)));
}

__global__ void prep_kernel(const float* __restrict__ q,
                            const float* __restrict__ kv_w,
                            const float* __restrict__ proj_w) {
    int tid = blockIdx.x * blockDim.x + threadIdx.x;
    int nth = gridDim.x * blockDim.x;
    for (int i = tid; i < 8192; i += nth) g_w2[i] = split2(kv_w[i]);
    for (int i = tid; i < 4096; i += nth) g_pw[i] = split2(proj_w[i]);
    for (int r = tid; r < 512; r += nth) {
        const float* qr = q + r * 64;
        float ss = 0.f;
#pragma unroll
        for (int p = 0; p < 64; p++) { float v = qr[p]; ss += v * v; }
        float inv = 1.f / fmaxf(sqrtf(ss), 1e-12f);
#pragma unroll
        for (int p = 0; p < 64; p++) g_q[r * 64 + p] = split2(qr[p] * inv);
    }
}

__device__ __forceinline__ void mma8(float (&d)[4], const unsigned (&a)[4], const unsigned (&b)[2]) {
    asm("mma.sync.aligned.m16n8k8.row.col.f32.tf32.tf32.f32 "
        "{%0,%1,%2,%3}, {%4,%5,%6,%7}, {%8,%9}, {%0,%1,%2,%3};"
        : "+f"(d[0]), "+f"(d[1]), "+f"(d[2]), "+f"(d[3])
        : "r"(a[0]), "r"(a[1]), "r"(a[2]), "r"(a[3]), "r"(b[0]), "r"(b[1]));
}

__device__ __forceinline__ void mma3(float (&d)[4], const unsigned (&ah)[4], const unsigned (&al)[4],
                                     const unsigned (&bh)[2], const unsigned (&bl)[2]) {
    mma8(d, al, bh);
    mma8(d, ah, bl);
    mma8(d, ah, bh);
}

// A fragment (16 rows x 8 k) from plain float smem, row-major lda, split on the fly.
__device__ __forceinline__ void ldA_s(const float* A, int lda, int m, int k, int g, int tq,
                                      unsigned (&ah)[4], unsigned (&al)[4]) {
    uint2 s;
    s = split2(A[(m + g) * lda + k + tq]);         ah[0] = s.x; al[0] = s.y;
    s = split2(A[(m + g + 8) * lda + k + tq]);     ah[1] = s.x; al[1] = s.y;
    s = split2(A[(m + g) * lda + k + tq + 4]);     ah[2] = s.x; al[2] = s.y;
    s = split2(A[(m + g + 8) * lda + k + tq + 4]); ah[3] = s.x; al[3] = s.y;
}
// A fragment from pre-split uint2 gmem.
__device__ __forceinline__ void ldA_g(const uint2* __restrict__ A, int lda, int m, int k, int g, int tq,
                                      unsigned (&ah)[4], unsigned (&al)[4]) {
    uint2 s;
    s = __ldg(&A[(m + g) * lda + k + tq]);         ah[0] = s.x; al[0] = s.y;
    s = __ldg(&A[(m + g + 8) * lda + k + tq]);     ah[1] = s.x; al[1] = s.y;
    s = __ldg(&A[(m + g) * lda + k + tq + 4]);     ah[2] = s.x; al[2] = s.y;
    s = __ldg(&A[(m + g + 8) * lda + k + tq + 4]); ah[3] = s.x; al[3] = s.y;
}
// B fragment (8 k x 8 n), element at B[k*bk + n*bn], plain smem, split on the fly.
__device__ __forceinline__ void ldB_s(const float* B, int bk, int bn, int n, int k, int g, int tq,
                                      unsigned (&bh)[2], unsigned (&bl)[2]) {
    uint2 s;
    s = split2(B[(k + tq) * bk + (n + g) * bn]);     bh[0] = s.x; bl[0] = s.y;
    s = split2(B[(k + tq + 4) * bk + (n + g) * bn]); bh[1] = s.x; bl[1] = s.y;
}
// B fragment from pre-split uint2 gmem.
__device__ __forceinline__ void ldB_g(const uint2* __restrict__ B, int bk, int bn, int n, int k, int g, int tq,
                                      unsigned (&bh)[2], unsigned (&bl)[2]) {
    uint2 s;
    s = __ldg(&B[(k + tq) * bk + (n + g) * bn]);     bh[0] = s.x; bl[0] = s.y;
    s = __ldg(&B[(k + tq + 4) * bk + (n + g) * bn]); bh[1] = s.x; bl[1] = s.y;
}

// smem (floats, stride 68 everywhere):
//   [0     : 4352)  X -> KN -> O
//   [4352  : 8704)  X(hi rows) ... actually X occupies [0:4352) only; V lives [4352:8704)
//   [8704  : 17408) T (128x68) -> S1 [8704:13056) + S2 [13056:17408)
// peak 17408 floats = 69,632 B -> 3 CTAs/SM
__global__ __launch_bounds__(256, 3) void win_kernel(
    const float* __restrict__ x,
    const float* __restrict__ dw_w,
    const float* __restrict__ rs1,
    const float* __restrict__ rs2,
    float* __restrict__ out)
{
    extern __shared__ float sm[];
    float* X  = sm;            // 64x68
    float* KN = sm;            // after dwconv (overwrites X)
    float* V  = sm + 4352;
    float* O  = sm;            // after S12 (overwrites KN)
    float* T  = sm + 8704;     // 128x68
    float* S1 = sm + 8704;     // after dwconv (overwrites T)
    float* S2 = sm + 13056;

    const int tid  = threadIdx.x;
    const int wid  = tid >> 5;
    const int lane = tid & 31;
    const int g = lane >> 2, tq = lane & 3;

    const int bw = blockIdx.x;
    const int b  = bw >> 10;
    const int w  = bw & 1023;
    const int wh = w >> 5, ww = w & 31;
    const float r1v = rs1[0], r2v = rs2[0];
    const uint2* __restrict__ qb = g_q + b * 4096;

    // ---- P0: load X window (roll -4 folded) ----
    const float* xb = x + (size_t)b * 64 * HH * WW_;
    for (int idx = tid; idx < 4096; idx += 256) {
        int c = idx >> 6, p = idx & 63;
        int gh = (wh * 8 + (p >> 3) + SHIFT) & 255;
        int gw = (ww * 8 + (p & 7) + SHIFT) & 255;
        X[c * 68 + p] = xb[(size_t)c * HH * WW_ + gh * WW_ + gw];
    }
    __syncthreads();

    // ---- P1: conv1x1  T(128x64) = W2 @ X ----
    {
        const int m0 = wid * 16;
        float acc[8][4];
#pragma unroll
        for (int i = 0; i < 8; i++)
#pragma unroll
            for (int j = 0; j < 4; j++) acc[i][j] = 0.f;
#pragma unroll
        for (int k0 = 0; k0 < 64; k0 += 8) {
            unsigned ah[4], al[4];
            ldA_g(g_w2, 64, m0, k0, g, tq, ah, al);
#pragma unroll
            for (int nt = 0; nt < 8; nt++) {
                unsigned bh[2], bl[2];
                ldB_s(X, 68, 1, nt * 8, k0, g, tq, bh, bl);
                mma3(acc[nt], ah, al, bh, bl);
            }
        }
#pragma unroll
        for (int nt = 0; nt < 8; nt++) {
            int c = nt * 8 + 2 * tq;
            T[(m0 + g) * 68 + c]         = acc[nt][0];
            T[(m0 + g) * 68 + c + 1]     = acc[nt][1];
            T[(m0 + g + 8) * 68 + c]     = acc[nt][2];
            T[(m0 + g + 8) * 68 + c + 1] = acc[nt][3];
        }
    }
    __syncthreads();

    // ---- P2: depthwise 3x3 -> KN (oc<64), V (oc>=64); overwrites X ----
    for (int task = tid; task < 1024; task += 256) {
        int oc = task >> 3, i = task & 7;
        const float* trow = T + oc * 68;
        float r[3][8];
#pragma unroll
        for (int dy = 0; dy < 3; dy++) {
            int ii = i + dy - 1;
            if (ii < 0 || ii > 7) {
#pragma unroll
                for (int j = 0; j < 8; j++) r[dy][j] = 0.f;
            } else {
                float4 v0 = *(const float4*)(trow + ii * 8);
                float4 v1 = *(const float4*)(trow + ii * 8 + 4);
                r[dy][0] = v0.x; r[dy][1] = v0.y; r[dy][2] = v0.z; r[dy][3] = v0.w;
                r[dy][4] = v1.x; r[dy][5] = v1.y; r[dy][6] = v1.z; r[dy][7] = v1.w;
            }
        }
        float wv[9];
#pragma unroll
        for (int q9 = 0; q9 < 9; q9++) wv[q9] = __ldg(&dw_w[oc * 9 + q9]);
        float o[8];
#pragma unroll
        for (int j = 0; j < 8; j++) {
            float s = 0.f;
#pragma unroll
            for (int dy = 0; dy < 3; dy++)
#pragma unroll
                for (int dx = 0; dx < 3; dx++) {
                    int jj = j + dx - 1;
                    if (jj < 0 || jj > 7) continue;
                    s = fmaf(wv[dy * 3 + dx], r[dy][jj], s);
                }
            o[j] = s;
        }
        float* dst = (oc < 64) ? (KN + oc * 68 + i * 8) : (V + (oc - 64) * 68 + i * 8);
        *(float4*)dst       = make_float4(o[0], o[1], o[2], o[3]);
        *(float4*)(dst + 4) = make_float4(o[4], o[5], o[6], o[7]);
    }
    __syncthreads();

    // ---- P3: l2norm rows of KN ----
    for (int r = wid; r < 64; r += 8) {
        float v0 = KN[r * 68 + lane], v1 = KN[r * 68 + 32 + lane];
        float ss = v0 * v0 + v1 * v1;
#pragma unroll
        for (int o = 16; o; o >>= 1) ss += __shfl_xor_sync(0xffffffffu, ss, o);
        float inv = 1.f / fmaxf(sqrtf(ss), 1e-12f);
        KN[r * 68 + lane] = v0 * inv;
        KN[r * 68 + 32 + lane] = v1 * inv;
    }
    __syncthreads();

    const int m0 = (wid & 3) * 16;
    const int n0 = (wid >> 2) * 32;

    // ---- P4: fused S1 = kn@qn^T, S2 = kn@v^T (shared A fragments) ----
    {
        float a1[4][4], a2[4][4];
#pragma unroll
        for (int i = 0; i < 4; i++)
#pragma unroll
            for (int j = 0; j < 4; j++) { a1[i][j] = 0.f; a2[i][j] = 0.f; }
#pragma unroll
        for (int k0 = 0; k0 < 64; k0 += 8) {
            unsigned ah[4], al[4];
            ldA_s(KN, 68, m0, k0, g, tq, ah, al);
#pragma unroll
            for (int nt = 0; nt < 4; nt++) {
                unsigned bh[2], bl[2];
                ldB_g(qb, 1, 64, n0 + nt * 8, k0, g, tq, bh, bl);   // qn[n][k]
                mma3(a1[nt], ah, al, bh, bl);
                ldB_s(V, 1, 68, n0 + nt * 8, k0, g, tq, bh, bl);    // v[n][k]
                mma3(a2[nt], ah, al, bh, bl);
            }
        }
#pragma unroll
        for (int nt = 0; nt < 4; nt++) {
            int c = n0 + nt * 8 + 2 * tq;
            S1[(m0 + g) * 68 + c]         = a1[nt][0] * r1v;
            S1[(m0 + g) * 68 + c + 1]     = a1[nt][1] * r1v;
            S1[(m0 + g + 8) * 68 + c]     = a1[nt][2] * r1v;
            S1[(m0 + g + 8) * 68 + c + 1] = a1[nt][3] * r1v;
            S2[(m0 + g) * 68 + c]         = a2[nt][0] * r2v;
            S2[(m0 + g) * 68 + c + 1]     = a2[nt][1] * r2v;
            S2[(m0 + g + 8) * 68 + c]     = a2[nt][2] * r2v;
            S2[(m0 + g + 8) * 68 + c + 1] = a2[nt][3] * r2v;
        }
    }
    __syncthreads();

    // ---- P5: softmax over 128 rows (S1 rows 0-63, S2 rows 64-127) ----
    for (int rr = wid; rr < 128; rr += 8) {
        float* Sr = (rr < 64) ? (S1 + rr * 68) : (S2 + (rr - 64) * 68);
        float v0 = Sr[lane], v1 = Sr[32 + lane];
        float m = fmaxf(v0, v1);
#pragma unroll
        for (int o = 16; o; o >>= 1) m = fmaxf(m, __shfl_xor_sync(0xffffffffu, m, o));
        float e0 = __expf(v0 - m), e1 = __expf(v1 - m);
        float s = e0 + e1;
#pragma unroll
        for (int o = 16; o; o >>= 1) s += __shfl_xor_sync(0xffffffffu, s, o);
        float inv = 1.f / s;
        Sr[lane] = e0 * inv;
        Sr[32 + lane] = e1 * inv;
    }
    __syncthreads();

    // ---- P6: fused out = A1@V + A2@Qn -> O (overwrites KN, disjoint from S/V) ----
    {
        float acc[4][4];
#pragma unroll
        for (int i = 0; i < 4; i++)
#pragma unroll
            for (int j = 0; j < 4; j++) acc[i][j] = 0.f;
#pragma unroll
        for (int k0 = 0; k0 < 64; k0 += 8) {
            unsigned ah1[4], al1[4], ah2[4], al2[4];
            ldA_s(S1, 68, m0, k0, g, tq, ah1, al1);
            ldA_s(S2, 68, m0, k0, g, tq, ah2, al2);
#pragma unroll
            for (int nt = 0; nt < 4; nt++) {
                unsigned bh[2], bl[2];
                ldB_s(V, 68, 1, n0 + nt * 8, k0, g, tq, bh, bl);    // v[k][n]
                mma3(acc[nt], ah1, al1, bh, bl);
                ldB_g(qb, 64, 1, n0 + nt * 8, k0, g, tq, bh, bl);   // qn[k][n]
                mma3(acc[nt], ah2, al2, bh, bl);
            }
        }
#pragma unroll
        for (int nt = 0; nt < 4; nt++) {
            int c = n0 + nt * 8 + 2 * tq;
            O[(m0 + g) * 68 + c]         = acc[nt][0];
            O[(m0 + g) * 68 + c + 1]     = acc[nt][1];
            O[(m0 + g + 8) * 68 + c]     = acc[nt][2];
            O[(m0 + g + 8) * 68 + c + 1] = acc[nt][3];
        }
    }
    __syncthreads();

    // ---- P7: proj y = PW @ O; store with roll +4 ----
    {
        float acc[4][4];
#pragma unroll
        for (int i = 0; i < 4; i++)
#pragma unroll
            for (int j = 0; j < 4; j++) acc[i][j] = 0.f;
#pragma unroll
        for (int k0 = 0; k0 < 64; k0 += 8) {
            unsigned ah[4], al[4];
            ldA_g(g_pw, 64, m0, k0, g, tq, ah, al);
#pragma unroll
            for (int nt = 0; nt < 4; nt++) {
                unsigned bh[2], bl[2];
                ldB_s(O, 68, 1, n0 + nt * 8, k0, g, tq, bh, bl);
                mma3(acc[nt], ah, al, bh, bl);
            }
        }
        float* ob = out + (size_t)b * 64 * HH * WW_;
#pragma unroll
        for (int nt = 0; nt < 4; nt++) {
            int c = n0 + nt * 8 + 2 * tq;
#pragma unroll
            for (int ri = 0; ri < 2; ri++) {
                int r = m0 + g + ri * 8;
#pragma unroll
                for (int ci = 0; ci < 2; ci++) {
                    int p = c + ci;
                    int gh = (wh * 8 + (p >> 3) + SHIFT) & 255;
                    int gw = (ww * 8 + (p & 7) + SHIFT) & 255;
                    ob[(size_t)r * HH * WW_ + gh * WW_ + gw] = acc[nt][ri * 2 + ci];
                }
            }
        }
    }
}

extern "C" void kernel_launch(void* const* d_in, const int* in_sizes, int n_in,
                              void* d_out, int out_size) {
    const float* x      = (const float*)d_in[0];
    const float* q      = (const float*)d_in[1];
    const float* kv_w   = (const float*)d_in[2];
    const float* dw_w   = (const float*)d_in[3];
    const float* proj_w = (const float*)d_in[4];
    const float* rs1    = (const float*)d_in[5];
    const float* rs2    = (const float*)d_in[6];
    float* out = (float*)d_out;

    static bool attr_set = false;
    const int smem_bytes = 17408 * 4;  // 69,632 B
    if (!attr_set) {
        cudaFuncSetAttribute(win_kernel,
                             cudaFuncAttributeMaxDynamicSharedMemorySize,
                             smem_bytes);
        attr_set = true;
    }

    prep_kernel<<<32, 256>>>(q, kv_w, proj_w);
    win_kernel<<<8192, 256, smem_bytes>>>(x, dw_w, rs1, rs2, out);
}

// round 4
// speedup vs baseline: 2.8833x; 1.7353x over previous
#include <cuda_runtime.h>
#include <math.h>

#define HH 256
#define WW_ 256
#define SHIFT 4
#define STR 36   // packed smem row stride (u32 words)

// Pre-split constants in gmem: uint2 = (bf16x2 hi-pair, bf16x2 lo-pair), pairs along k
__device__ uint2 g_w2p[128 * 32];      // kv_w [oc][c-pair]
__device__ uint2 g_pwp[64 * 32];       // proj_w [oc][c-pair]
__device__ uint2 g_qp[8 * 64 * 32];    // qn [b][c][p-pair]   (k = p)
__device__ uint2 g_qc[8 * 64 * 32];    // qn [b][p][c-pair]   (k = c)
__device__ float g_qnf[8 * 64 * 64];

__device__ __forceinline__ unsigned pack_bf2(float v0, float v1) {
    unsigned d;
    asm("cvt.rn.bf16x2.f32 %0, %1, %2;" : "=r"(d) : "f"(v1), "f"(v0));  // lo16=v0, hi16=v1
    return d;
}
__device__ __forceinline__ uint2 split_pair(float v0, float v1) {
    unsigned h = pack_bf2(v0, v1);
    float h0 = __uint_as_float(h << 16);
    float h1 = __uint_as_float(h & 0xffff0000u);
    return make_uint2(h, pack_bf2(v0 - h0, v1 - h1));
}

__global__ void prep1(const float* __restrict__ q,
                      const float* __restrict__ kv_w,
                      const float* __restrict__ proj_w) {
    int gt = blockIdx.x * blockDim.x + threadIdx.x;  // 512 threads
    for (int i = gt; i < 4096; i += 512) {
        int oc = i >> 5, cw = i & 31;
        g_w2p[i] = split_pair(kv_w[oc * 64 + 2 * cw], kv_w[oc * 64 + 2 * cw + 1]);
    }
    for (int i = gt; i < 2048; i += 512) {
        int oc = i >> 5, cw = i & 31;
        g_pwp[i] = split_pair(proj_w[oc * 64 + 2 * cw], proj_w[oc * 64 + 2 * cw + 1]);
    }
    if (gt < 512) {
        const float* qr = q + gt * 64;
        float ss = 0.f;
#pragma unroll
        for (int p = 0; p < 64; p++) { float v = qr[p]; ss += v * v; }
        float inv = 1.f / fmaxf(sqrtf(ss), 1e-12f);
#pragma unroll
        for (int pw = 0; pw < 32; pw++) {
            float v0 = qr[2 * pw] * inv, v1 = qr[2 * pw + 1] * inv;
            g_qnf[gt * 64 + 2 * pw] = v0;
            g_qnf[gt * 64 + 2 * pw + 1] = v1;
            g_qp[gt * 32 + pw] = split_pair(v0, v1);
        }
    }
}
__global__ void prep2() {
    int gt = blockIdx.x * blockDim.x + threadIdx.x;  // 4096 threads
    for (int idx = gt; idx < 16384; idx += 4096) {
        int b = idx >> 11, rem = idx & 2047;
        int p = rem >> 5, cw = rem & 31;
        float v0 = g_qnf[(b * 64 + 2 * cw) * 64 + p];
        float v1 = g_qnf[(b * 64 + 2 * cw + 1) * 64 + p];
        g_qc[idx] = split_pair(v0, v1);
    }
}

__device__ __forceinline__ void mma16(float (&d)[4], const unsigned (&a)[4], const unsigned (&b)[2]) {
    asm("mma.sync.aligned.m16n8k16.row.col.f32.bf16.bf16.f32 "
        "{%0,%1,%2,%3}, {%4,%5,%6,%7}, {%8,%9}, {%0,%1,%2,%3};"
        : "+f"(d[0]), "+f"(d[1]), "+f"(d[2]), "+f"(d[3])
        : "r"(a[0]), "r"(a[1]), "r"(a[2]), "r"(a[3]), "r"(b[0]), "r"(b[1]));
}
__device__ __forceinline__ void mma3(float (&d)[4], const unsigned (&ah)[4], const unsigned (&al)[4],
                                     const unsigned (&bh)[2], const unsigned (&bl)[2]) {
    mma16(d, al, bh);
    mma16(d, ah, bl);
    mma16(d, ah, bh);
}

// smem u32 layout (total 18432 u32 = 73728 B):
//  [0,2304)      XC_H    -> A1_H
//  [2304,4608)   XC_L    -> A1_L
//  [4608,9216)   KN_H/KN_L -> O f32 (64x68 @4608)
//  [9216,13824)  V_H/V_L   -> OC_H/OC_L
//  [13824,18432) A2_H/A2_L
__global__ __launch_bounds__(256, 3) void win_kernel(
    const float* __restrict__ x,
    const float* __restrict__ dw_w,
    const float* __restrict__ rs1,
    const float* __restrict__ rs2,
    float* __restrict__ out)
{
    extern __shared__ unsigned su[];
    unsigned* XH = su;
    unsigned* XL = su + 2304;
    unsigned* A1H = su;            // after P3
    unsigned* A1L = su + 2304;
    unsigned* KNH = su + 4608;
    unsigned* KNL = su + 6912;
    float*    O   = (float*)(su + 4608);
    unsigned* VH  = su + 9216;
    unsigned* VL  = su + 11520;
    unsigned* OCH = su + 9216;     // after P5
    unsigned* OCL = su + 11520;
    unsigned* A2H = su + 13824;
    unsigned* A2L = su + 16128;

    const int tid  = threadIdx.x;
    const int wid  = tid >> 5;
    const int lane = tid & 31;
    const int g = lane >> 2, tq = lane & 3;
    const unsigned FULL = 0xffffffffu;

    const int bw = blockIdx.x;
    const int b  = bw >> 10;
    const int w  = bw & 1023;
    const int wh = w >> 5, ww = w & 31;
    const float r1v = rs1[0], r2v = rs2[0];
    const uint2* __restrict__ qpb = g_qp + b * 2048;
    const uint2* __restrict__ qcb = g_qc + b * 2048;

    // ---- P0: load X window (roll -4), pack pairs along c -> XC[p][cw] ----
    const float* xb = x + (size_t)b * 64 * HH * WW_;
    for (int idx = tid; idx < 2048; idx += 256) {
        int p = idx & 63, cw = idx >> 6;
        int gh = (wh * 8 + (p >> 3) + SHIFT) & 255;
        int gw = (ww * 8 + (p & 7) + SHIFT) & 255;
        size_t off = (size_t)gh * WW_ + gw;
        float v0 = xb[(size_t)(2 * cw) * HH * WW_ + off];
        float v1 = xb[(size_t)(2 * cw + 1) * HH * WW_ + off];
        uint2 pr = split_pair(v0, v1);
        XH[p * STR + cw] = pr.x;
        XL[p * STR + cw] = pr.y;
    }
    __syncthreads();

    // ---- P2: conv1x1 (regs) + in-register dwconv + norm + pack KN/V ----
    {
        const int m0 = wid * 16;
        float acc[8][4];
#pragma unroll
        for (int i = 0; i < 8; i++)
#pragma unroll
            for (int j = 0; j < 4; j++) acc[i][j] = 0.f;
#pragma unroll
        for (int s = 0; s < 4; s++) {
            int kw = 8 * s;
            uint2 a0 = __ldg(&g_w2p[(m0 + g) * 32 + tq + kw]);
            uint2 a1 = __ldg(&g_w2p[(m0 + g + 8) * 32 + tq + kw]);
            uint2 a2 = __ldg(&g_w2p[(m0 + g) * 32 + tq + 4 + kw]);
            uint2 a3 = __ldg(&g_w2p[(m0 + g + 8) * 32 + tq + 4 + kw]);
            unsigned ah[4] = {a0.x, a1.x, a2.x, a3.x};
            unsigned al[4] = {a0.y, a1.y, a2.y, a3.y};
#pragma unroll
            for (int nt = 0; nt < 8; nt++) {
                int rb = (8 * nt + g) * STR + tq + kw;
                unsigned bh[2] = {XH[rb], XH[rb + 4]};
                unsigned bl[2] = {XL[rb], XL[rb + 4]};
                mma3(acc[nt], ah, al, bh, bl);
            }
        }
        // dwconv per m-half
#pragma unroll
        for (int h = 0; h < 2; h++) {
            const int oc = m0 + 8 * h + g;
            float wv[9];
#pragma unroll
            for (int q9 = 0; q9 < 9; q9++) wv[q9] = __ldg(&dw_w[oc * 9 + q9]);
            float o0[8], o1[8];
#pragma unroll
            for (int i = 0; i < 8; i++) { o0[i] = 0.f; o1[i] = 0.f; }
#pragma unroll
            for (int ii = 0; ii < 8; ii++) {
                float c0 = acc[ii][2 * h], c1 = acc[ii][2 * h + 1];
                float Lv = __shfl_up_sync(FULL, c1, 1);
                float Rv = __shfl_down_sync(FULL, c0, 1);
                if (tq == 0) Lv = 0.f;
                if (tq == 3) Rv = 0.f;
#pragma unroll
                for (int dy = 0; dy < 3; dy++) {
                    int i = ii + 1 - dy;
                    if (i < 0 || i > 7) continue;
                    o0[i] = fmaf(wv[dy * 3 + 0], Lv, fmaf(wv[dy * 3 + 1], c0, fmaf(wv[dy * 3 + 2], c1, o0[i])));
                    o1[i] = fmaf(wv[dy * 3 + 0], c0, fmaf(wv[dy * 3 + 1], c1, fmaf(wv[dy * 3 + 2], Rv, o1[i])));
                }
            }
            unsigned* DH; unsigned* DL; int row;
            if (wid < 4) {   // K: l2-normalize rows
                float ss = 0.f;
#pragma unroll
                for (int i = 0; i < 8; i++) ss += o0[i] * o0[i] + o1[i] * o1[i];
                ss += __shfl_xor_sync(FULL, ss, 1);
                ss += __shfl_xor_sync(FULL, ss, 2);
                float inv = 1.f / fmaxf(sqrtf(ss), 1e-12f);
#pragma unroll
                for (int i = 0; i < 8; i++) { o0[i] *= inv; o1[i] *= inv; }
                DH = KNH; DL = KNL; row = oc;
            } else {
                DH = VH; DL = VL; row = oc - 64;
            }
#pragma unroll
            for (int i = 0; i < 8; i++) {
                uint2 pr = split_pair(o0[i], o1[i]);
                DH[row * STR + 4 * i + tq] = pr.x;
                DL[row * STR + 4 * i + tq] = pr.y;
            }
        }
    }
    __syncthreads();

    // ---- P3: S-GEMM (S1 or S2 per warp) + in-register softmax + pack A ----
    {
        const int mat = wid >> 2;
        const int m0 = (wid & 3) * 16;
        const float rv = mat ? r2v : r1v;
        float acc[8][4];
#pragma unroll
        for (int i = 0; i < 8; i++)
#pragma unroll
            for (int j = 0; j < 4; j++) acc[i][j] = 0.f;
#pragma unroll
        for (int s = 0; s < 4; s++) {
            int kw = 8 * s;
            int ra = (m0 + g) * STR + tq + kw;
            int rb2 = (m0 + g + 8) * STR + tq + kw;
            unsigned ah[4] = {KNH[ra], KNH[rb2], KNH[ra + 4], KNH[rb2 + 4]};
            unsigned al[4] = {KNL[ra], KNL[rb2], KNL[ra + 4], KNL[rb2 + 4]};
#pragma unroll
            for (int nt = 0; nt < 8; nt++) {
                unsigned bh[2], bl[2];
                if (mat == 0) {
                    uint2 q0 = __ldg(&qpb[(8 * nt + g) * 32 + tq + kw]);
                    uint2 q1 = __ldg(&qpb[(8 * nt + g) * 32 + tq + 4 + kw]);
                    bh[0] = q0.x; bh[1] = q1.x; bl[0] = q0.y; bl[1] = q1.y;
                } else {
                    int rbv = (8 * nt + g) * STR + tq + kw;
                    bh[0] = VH[rbv]; bh[1] = VH[rbv + 4];
                    bl[0] = VL[rbv]; bl[1] = VL[rbv + 4];
                }
                mma3(acc[nt], ah, al, bh, bl);
            }
        }
        unsigned* DH = mat ? A2H : A1H;
        unsigned* DL = mat ? A2L : A1L;
#pragma unroll
        for (int h = 0; h < 2; h++) {
            float m = -1e30f;
#pragma unroll
            for (int nt = 0; nt < 8; nt++) {
                acc[nt][2 * h] *= rv; acc[nt][2 * h + 1] *= rv;
                m = fmaxf(m, fmaxf(acc[nt][2 * h], acc[nt][2 * h + 1]));
            }
            m = fmaxf(m, __shfl_xor_sync(FULL, m, 1));
            m = fmaxf(m, __shfl_xor_sync(FULL, m, 2));
            float s = 0.f;
            float e[16];
#pragma unroll
            for (int nt = 0; nt < 8; nt++) {
                e[2 * nt]     = __expf(acc[nt][2 * h] - m);
                e[2 * nt + 1] = __expf(acc[nt][2 * h + 1] - m);
                s += e[2 * nt] + e[2 * nt + 1];
            }
            s += __shfl_xor_sync(FULL, s, 1);
            s += __shfl_xor_sync(FULL, s, 2);
            float inv = 1.f / s;
            int row = m0 + g + 8 * h;
#pragma unroll
            for (int nt = 0; nt < 8; nt++) {
                uint2 pr = split_pair(e[2 * nt] * inv, e[2 * nt + 1] * inv);
                DH[row * STR + 4 * nt + tq] = pr.x;
                DL[row * STR + 4 * nt + tq] = pr.y;
            }
        }
    }
    __syncthreads();

    // ---- P4: out = A1@V + A2@Qn -> O f32 (KN region) ----
    {
        const int m0 = (wid & 3) * 16;
        const int n0 = (wid >> 2) * 32;
        const unsigned sel = (g & 1) ? 0x7632u : 0x5410u;
        float acc[4][4];
#pragma unroll
        for (int i = 0; i < 4; i++)
#pragma unroll
            for (int j = 0; j < 4; j++) acc[i][j] = 0.f;
#pragma unroll
        for (int s = 0; s < 4; s++) {
            int kw = 8 * s;
            int ra = (m0 + g) * STR + tq + kw;
            int rb2 = (m0 + g + 8) * STR + tq + kw;
            unsigned a1h[4] = {A1H[ra], A1H[rb2], A1H[ra + 4], A1H[rb2 + 4]};
            unsigned a1l[4] = {A1L[ra], A1L[rb2], A1L[ra + 4], A1L[rb2 + 4]};
            unsigned a2h[4] = {A2H[ra], A2H[rb2], A2H[ra + 4], A2H[rb2 + 4]};
            unsigned a2l[4] = {A2L[ra], A2L[rb2], A2L[ra + 4], A2L[rb2 + 4]};
#pragma unroll
            for (int nt = 0; nt < 4; nt++) {
                int colw = (n0 + 8 * nt + g) >> 1;
                // out1 B: V transposed via PRMT
                int r0 = (2 * tq + 16 * s) * STR + colw;
                int r1 = (2 * tq + 8 + 16 * s) * STR + colw;
                unsigned bh[2], bl[2];
                bh[0] = __byte_perm(VH[r0], VH[r0 + STR], sel);
                bh[1] = __byte_perm(VH[r1], VH[r1 + STR], sel);
                bl[0] = __byte_perm(VL[r0], VL[r0 + STR], sel);
                bl[1] = __byte_perm(VL[r1], VL[r1 + STR], sel);
                mma3(acc[nt], a1h, a1l, bh, bl);
                // out2 B: qn c-packed from gmem
                uint2 q0 = __ldg(&qcb[(n0 + 8 * nt + g) * 32 + tq + kw]);
                uint2 q1 = __ldg(&qcb[(n0 + 8 * nt + g) * 32 + tq + 4 + kw]);
                bh[0] = q0.x; bh[1] = q1.x; bl[0] = q0.y; bl[1] = q1.y;
                mma3(acc[nt], a2h, a2l, bh, bl);
            }
        }
#pragma unroll
        for (int nt = 0; nt < 4; nt++) {
            int c = n0 + 8 * nt + 2 * tq;
            O[(m0 + g) * 68 + c]         = acc[nt][0];
            O[(m0 + g) * 68 + c + 1]     = acc[nt][1];
            O[(m0 + g + 8) * 68 + c]     = acc[nt][2];
            O[(m0 + g + 8) * 68 + c + 1] = acc[nt][3];
        }
    }
    __syncthreads();

    // ---- P5: pack O (f32 [c][p]) -> OC packed [p][c-pair] (V region) ----
    for (int idx = tid; idx < 2048; idx += 256) {
        int p = idx & 63, cw = idx >> 6;
        float v0 = O[(2 * cw) * 68 + p];
        float v1 = O[(2 * cw + 1) * 68 + p];
        uint2 pr = split_pair(v0, v1);
        OCH[p * STR + cw] = pr.x;
        OCL[p * STR + cw] = pr.y;
    }
    __syncthreads();

    // ---- P6: proj y = PW @ O -> gmem (roll +4) ----
    {
        const int m0 = (wid & 3) * 16;
        const int n0 = (wid >> 2) * 32;
        float acc[4][4];
#pragma unroll
        for (int i = 0; i < 4; i++)
#pragma unroll
            for (int j = 0; j < 4; j++) acc[i][j] = 0.f;
#pragma unroll
        for (int s = 0; s < 4; s++) {
            int kw = 8 * s;
            uint2 a0 = __ldg(&g_pwp[(m0 + g) * 32 + tq + kw]);
            uint2 a1 = __ldg(&g_pwp[(m0 + g + 8) * 32 + tq + kw]);
            uint2 a2 = __ldg(&g_pwp[(m0 + g) * 32 + tq + 4 + kw]);
            uint2 a3 = __ldg(&g_pwp[(m0 + g + 8) * 32 + tq + 4 + kw]);
            unsigned ah[4] = {a0.x, a1.x, a2.x, a3.x};
            unsigned al[4] = {a0.y, a1.y, a2.y, a3.y};
#pragma unroll
            for (int nt = 0; nt < 4; nt++) {
                int rb = (n0 + 8 * nt + g) * STR + tq + kw;
                unsigned bh[2] = {OCH[rb], OCH[rb + 4]};
                unsigned bl[2] = {OCL[rb], OCL[rb + 4]};
                mma3(acc[nt], ah, al, bh, bl);
            }
        }
        float* ob = out + (size_t)b * 64 * HH * WW_;
#pragma unroll
        for (int nt = 0; nt < 4; nt++) {
            int c = n0 + 8 * nt + 2 * tq;
#pragma unroll
            for (int ri = 0; ri < 2; ri++) {
                int r = (m0 + g) + ri * 8;
#pragma unroll
                for (int ci = 0; ci < 2; ci++) {
                    int p = c + ci;
                    int gh = (wh * 8 + (p >> 3) + SHIFT) & 255;
                    int gw = (ww * 8 + (p & 7) + SHIFT) & 255;
                    ob[(size_t)r * HH * WW_ + gh * WW_ + gw] = acc[nt][ri * 2 + ci];
                }
            }
        }
    }
}

extern "C" void kernel_launch(void* const* d_in, const int* in_sizes, int n_in,
                              void* d_out, int out_size) {
    const float* x      = (const float*)d_in[0];
    const float* q      = (const float*)d_in[1];
    const float* kv_w   = (const float*)d_in[2];
    const float* dw_w   = (const float*)d_in[3];
    const float* proj_w = (const float*)d_in[4];
    const float* rs1    = (const float*)d_in[5];
    const float* rs2    = (const float*)d_in[6];
    float* out = (float*)d_out;

    static bool attr_set = false;
    const int smem_bytes = 18432 * 4;  // 73,728 B
    if (!attr_set) {
        cudaFuncSetAttribute(win_kernel,
                             cudaFuncAttributeMaxDynamicSharedMemorySize,
                             smem_bytes);
        attr_set = true;
    }

    prep1<<<2, 256>>>(q, kv_w, proj_w);
    prep2<<<16, 256>>>();
    win_kernel<<<8192, 256, smem_bytes>>>(x, dw_w, rs1, rs2, out);
}

// round 5
// speedup vs baseline: 3.2862x; 1.1397x over previous
#include <cuda_runtime.h>
#include <math.h>

#define HH 256
#define WW_ 256
#define SHIFT 4
#define STR 36   // packed smem row stride (u32 words)

// Pre-split constants in gmem: uint2 = (bf16x2 hi-pair, bf16x2 lo-pair), pairs along k
__device__ uint2 g_w2p[128 * 32];      // kv_w [oc][c-pair]
__device__ uint2 g_pwp[64 * 32];       // proj_w [oc][c-pair]
__device__ uint2 g_qp[8 * 64 * 32];    // qn [b][c][p-pair]   (k = p)
__device__ uint2 g_qc[8 * 64 * 32];    // qn [b][p][c-pair]   (k = c)
__device__ float g_qnf[8 * 64 * 64];

__device__ __forceinline__ unsigned pack_bf2(float v0, float v1) {
    unsigned d;
    asm("cvt.rn.bf16x2.f32 %0, %1, %2;" : "=r"(d) : "f"(v1), "f"(v0));  // lo16=v0, hi16=v1
    return d;
}
__device__ __forceinline__ uint2 split_pair(float v0, float v1) {
    unsigned h = pack_bf2(v0, v1);
    float h0 = __uint_as_float(h << 16);
    float h1 = __uint_as_float(h & 0xffff0000u);
    return make_uint2(h, pack_bf2(v0 - h0, v1 - h1));
}

// One warp per (b,c) row: l2-normalize q, emit g_qnf + g_qp.
__global__ void prep_q(const float* __restrict__ q) {
    int warp = (blockIdx.x * blockDim.x + threadIdx.x) >> 5;
    int lane = threadIdx.x & 31;
    if (warp >= 512) return;
    const float* qr = q + warp * 64;
    float v0 = qr[2 * lane], v1 = qr[2 * lane + 1];
    float ss = v0 * v0 + v1 * v1;
#pragma unroll
    for (int o = 16; o; o >>= 1) ss += __shfl_xor_sync(0xffffffffu, ss, o);
    float inv = 1.f / fmaxf(sqrtf(ss), 1e-12f);
    v0 *= inv; v1 *= inv;
    g_qnf[warp * 64 + 2 * lane] = v0;
    g_qnf[warp * 64 + 2 * lane + 1] = v1;
    g_qp[warp * 32 + lane] = split_pair(v0, v1);
}

// Wide: build w2p, pwp, qc (qc reads g_qnf written by prep_q).
__global__ void prep_rest(const float* __restrict__ kv_w,
                          const float* __restrict__ proj_w) {
    int gt = blockIdx.x * blockDim.x + threadIdx.x;  // 4096 threads
    if (gt < 4096) {
        int oc = gt >> 5, cw = gt & 31;
        g_w2p[gt] = split_pair(kv_w[oc * 64 + 2 * cw], kv_w[oc * 64 + 2 * cw + 1]);
    }
    if (gt < 2048) {
        int oc = gt >> 5, cw = gt & 31;
        g_pwp[gt] = split_pair(proj_w[oc * 64 + 2 * cw], proj_w[oc * 64 + 2 * cw + 1]);
    }
    for (int idx = gt; idx < 16384; idx += 4096) {
        int b = idx >> 11, rem = idx & 2047;
        int p = rem >> 5, cw = rem & 31;
        float v0 = g_qnf[(b * 64 + 2 * cw) * 64 + p];
        float v1 = g_qnf[(b * 64 + 2 * cw + 1) * 64 + p];
        g_qc[idx] = split_pair(v0, v1);
    }
}

__device__ __forceinline__ void mma16(float (&d)[4], const unsigned (&a)[4], const unsigned (&b)[2]) {
    asm("mma.sync.aligned.m16n8k16.row.col.f32.bf16.bf16.f32 "
        "{%0,%1,%2,%3}, {%4,%5,%6,%7}, {%8,%9}, {%0,%1,%2,%3};"
        : "+f"(d[0]), "+f"(d[1]), "+f"(d[2]), "+f"(d[3])
        : "r"(a[0]), "r"(a[1]), "r"(a[2]), "r"(a[3]), "r"(b[0]), "r"(b[1]));
}
__device__ __forceinline__ void mma3(float (&d)[4], const unsigned (&ah)[4], const unsigned (&al)[4],
                                     const unsigned (&bh)[2], const unsigned (&bl)[2]) {
    mma16(d, al, bh);
    mma16(d, ah, bl);
    mma16(d, ah, bh);
}

// smem u32 layout (total 18432 u32 = 73728 B):
//  [0,4608)      XC_H/XC_L  -> A1_H/A1_L
//  [4608,9216)   KN_H/KN_L  -> OC_H/OC_L (packed O, written in P4 epilogue)
//  [9216,13824)  V_H/V_L
//  [13824,18432) A2_H/A2_L
__global__ __launch_bounds__(256, 3) void win_kernel(
    const float* __restrict__ x,
    const float* __restrict__ dw_w,
    const float* __restrict__ rs1,
    const float* __restrict__ rs2,
    float* __restrict__ out)
{
    extern __shared__ unsigned su[];
    unsigned* XH = su;
    unsigned* XL = su + 2304;
    unsigned* A1H = su;            // after P3
    unsigned* A1L = su + 2304;
    unsigned* KNH = su + 4608;
    unsigned* KNL = su + 6912;
    unsigned* OCH = su + 4608;     // after P4 (KN dead)
    unsigned* OCL = su + 6912;
    unsigned* VH  = su + 9216;
    unsigned* VL  = su + 11520;
    unsigned* A2H = su + 13824;
    unsigned* A2L = su + 16128;

    const int tid  = threadIdx.x;
    const int wid  = tid >> 5;
    const int lane = tid & 31;
    const int g = lane >> 2, tq = lane & 3;
    const unsigned FULL = 0xffffffffu;

    const int bw = blockIdx.x;
    const int b  = bw >> 10;
    const int w  = bw & 1023;
    const int wh = w >> 5, ww = w & 31;
    const float r1v = rs1[0], r2v = rs2[0];
    const uint2* __restrict__ qpb = g_qp + b * 2048;
    const uint2* __restrict__ qcb = g_qc + b * 2048;

    // ---- P0: load X window (roll -4), pack pairs along c -> XC[p][cw] ----
    const float* xb = x + (size_t)b * 64 * HH * WW_;
    for (int idx = tid; idx < 2048; idx += 256) {
        int p = idx & 63, cw = idx >> 6;
        int gh = (wh * 8 + (p >> 3) + SHIFT) & 255;
        int gw = (ww * 8 + (p & 7) + SHIFT) & 255;
        size_t off = (size_t)gh * WW_ + gw;
        float v0 = xb[(size_t)(2 * cw) * HH * WW_ + off];
        float v1 = xb[(size_t)(2 * cw + 1) * HH * WW_ + off];
        uint2 pr = split_pair(v0, v1);
        XH[p * STR + cw] = pr.x;
        XL[p * STR + cw] = pr.y;
    }
    __syncthreads();

    // ---- P2: conv1x1 (regs) + in-register dwconv + norm + pack KN/V ----
    {
        const int m0 = wid * 16;
        float acc[8][4];
#pragma unroll
        for (int i = 0; i < 8; i++)
#pragma unroll
            for (int j = 0; j < 4; j++) acc[i][j] = 0.f;
#pragma unroll
        for (int s = 0; s < 4; s++) {
            int kw = 8 * s;
            uint2 a0 = __ldg(&g_w2p[(m0 + g) * 32 + tq + kw]);
            uint2 a1 = __ldg(&g_w2p[(m0 + g + 8) * 32 + tq + kw]);
            uint2 a2 = __ldg(&g_w2p[(m0 + g) * 32 + tq + 4 + kw]);
            uint2 a3 = __ldg(&g_w2p[(m0 + g + 8) * 32 + tq + 4 + kw]);
            unsigned ah[4] = {a0.x, a1.x, a2.x, a3.x};
            unsigned al[4] = {a0.y, a1.y, a2.y, a3.y};
#pragma unroll
            for (int nt = 0; nt < 8; nt++) {
                int rb = (8 * nt + g) * STR + tq + kw;
                unsigned bh[2] = {XH[rb], XH[rb + 4]};
                unsigned bl[2] = {XL[rb], XL[rb + 4]};
                mma3(acc[nt], ah, al, bh, bl);
            }
        }
        // dwconv per m-half
#pragma unroll
        for (int h = 0; h < 2; h++) {
            const int oc = m0 + 8 * h + g;
            float wv[9];
#pragma unroll
            for (int q9 = 0; q9 < 9; q9++) wv[q9] = __ldg(&dw_w[oc * 9 + q9]);
            float o0[8], o1[8];
#pragma unroll
            for (int i = 0; i < 8; i++) { o0[i] = 0.f; o1[i] = 0.f; }
#pragma unroll
            for (int ii = 0; ii < 8; ii++) {
                float c0 = acc[ii][2 * h], c1 = acc[ii][2 * h + 1];
                float Lv = __shfl_up_sync(FULL, c1, 1);
                float Rv = __shfl_down_sync(FULL, c0, 1);
                if (tq == 0) Lv = 0.f;
                if (tq == 3) Rv = 0.f;
#pragma unroll
                for (int dy = 0; dy < 3; dy++) {
                    int i = ii + 1 - dy;
                    if (i < 0 || i > 7) continue;
                    o0[i] = fmaf(wv[dy * 3 + 0], Lv, fmaf(wv[dy * 3 + 1], c0, fmaf(wv[dy * 3 + 2], c1, o0[i])));
                    o1[i] = fmaf(wv[dy * 3 + 0], c0, fmaf(wv[dy * 3 + 1], c1, fmaf(wv[dy * 3 + 2], Rv, o1[i])));
                }
            }
            unsigned* DH; unsigned* DL; int row;
            if (wid < 4) {   // K: l2-normalize rows
                float ss = 0.f;
#pragma unroll
                for (int i = 0; i < 8; i++) ss += o0[i] * o0[i] + o1[i] * o1[i];
                ss += __shfl_xor_sync(FULL, ss, 1);
                ss += __shfl_xor_sync(FULL, ss, 2);
                float inv = 1.f / fmaxf(sqrtf(ss), 1e-12f);
#pragma unroll
                for (int i = 0; i < 8; i++) { o0[i] *= inv; o1[i] *= inv; }
                DH = KNH; DL = KNL; row = oc;
            } else {
                DH = VH; DL = VL; row = oc - 64;
            }
#pragma unroll
            for (int i = 0; i < 8; i++) {
                uint2 pr = split_pair(o0[i], o1[i]);
                DH[row * STR + 4 * i + tq] = pr.x;
                DL[row * STR + 4 * i + tq] = pr.y;
            }
        }
    }
    __syncthreads();

    // ---- P3: S-GEMM (S1 or S2 per warp) + in-register softmax + pack A ----
    {
        const int mat = wid >> 2;
        const int m0 = (wid & 3) * 16;
        const float rv = mat ? r2v : r1v;
        float acc[8][4];
#pragma unroll
        for (int i = 0; i < 8; i++)
#pragma unroll
            for (int j = 0; j < 4; j++) acc[i][j] = 0.f;
#pragma unroll
        for (int s = 0; s < 4; s++) {
            int kw = 8 * s;
            int ra = (m0 + g) * STR + tq + kw;
            int rb2 = (m0 + g + 8) * STR + tq + kw;
            unsigned ah[4] = {KNH[ra], KNH[rb2], KNH[ra + 4], KNH[rb2 + 4]};
            unsigned al[4] = {KNL[ra], KNL[rb2], KNL[ra + 4], KNL[rb2 + 4]};
#pragma unroll
            for (int nt = 0; nt < 8; nt++) {
                unsigned bh[2], bl[2];
                if (mat == 0) {
                    uint2 q0 = __ldg(&qpb[(8 * nt + g) * 32 + tq + kw]);
                    uint2 q1 = __ldg(&qpb[(8 * nt + g) * 32 + tq + 4 + kw]);
                    bh[0] = q0.x; bh[1] = q1.x; bl[0] = q0.y; bl[1] = q1.y;
                } else {
                    int rbv = (8 * nt + g) * STR + tq + kw;
                    bh[0] = VH[rbv]; bh[1] = VH[rbv + 4];
                    bl[0] = VL[rbv]; bl[1] = VL[rbv + 4];
                }
                mma3(acc[nt], ah, al, bh, bl);
            }
        }
        unsigned* DH = mat ? A2H : A1H;
        unsigned* DL = mat ? A2L : A1L;
#pragma unroll
        for (int h = 0; h < 2; h++) {
            float m = -1e30f;
#pragma unroll
            for (int nt = 0; nt < 8; nt++) {
                acc[nt][2 * h] *= rv; acc[nt][2 * h + 1] *= rv;
                m = fmaxf(m, fmaxf(acc[nt][2 * h], acc[nt][2 * h + 1]));
            }
            m = fmaxf(m, __shfl_xor_sync(FULL, m, 1));
            m = fmaxf(m, __shfl_xor_sync(FULL, m, 2));
            float s = 0.f;
            float e[16];
#pragma unroll
            for (int nt = 0; nt < 8; nt++) {
                e[2 * nt]     = __expf(acc[nt][2 * h] - m);
                e[2 * nt + 1] = __expf(acc[nt][2 * h + 1] - m);
                s += e[2 * nt] + e[2 * nt + 1];
            }
            s += __shfl_xor_sync(FULL, s, 1);
            s += __shfl_xor_sync(FULL, s, 2);
            float inv = 1.f / s;
            int row = m0 + g + 8 * h;
#pragma unroll
            for (int nt = 0; nt < 8; nt++) {
                uint2 pr = split_pair(e[2 * nt] * inv, e[2 * nt + 1] * inv);
                DH[row * STR + 4 * nt + tq] = pr.x;
                DL[row * STR + 4 * nt + tq] = pr.y;
            }
        }
    }
    __syncthreads();

    // ---- P4: out = A1@V + A2@Qn; epilogue packs O pairs-along-c via shfl -> OC ----
    {
        const int m0 = (wid & 3) * 16;
        const int n0 = (wid >> 2) * 32;
        const unsigned sel = (g & 1) ? 0x7632u : 0x5410u;
        float acc[4][4];
#pragma unroll
        for (int i = 0; i < 4; i++)
#pragma unroll
            for (int j = 0; j < 4; j++) acc[i][j] = 0.f;
#pragma unroll
        for (int s = 0; s < 4; s++) {
            int kw = 8 * s;
            int ra = (m0 + g) * STR + tq + kw;
            int rb2 = (m0 + g + 8) * STR + tq + kw;
            unsigned a1h[4] = {A1H[ra], A1H[rb2], A1H[ra + 4], A1H[rb2 + 4]};
            unsigned a1l[4] = {A1L[ra], A1L[rb2], A1L[ra + 4], A1L[rb2 + 4]};
            unsigned a2h[4] = {A2H[ra], A2H[rb2], A2H[ra + 4], A2H[rb2 + 4]};
            unsigned a2l[4] = {A2L[ra], A2L[rb2], A2L[ra + 4], A2L[rb2 + 4]};
#pragma unroll
            for (int nt = 0; nt < 4; nt++) {
                int colw = (n0 + 8 * nt + g) >> 1;
                // out1 B: V transposed via PRMT
                int r0 = (2 * tq + 16 * s) * STR + colw;
                int r1 = (2 * tq + 8 + 16 * s) * STR + colw;
                unsigned bh[2], bl[2];
                bh[0] = __byte_perm(VH[r0], VH[r0 + STR], sel);
                bh[1] = __byte_perm(VH[r1], VH[r1 + STR], sel);
                bl[0] = __byte_perm(VL[r0], VL[r0 + STR], sel);
                bl[1] = __byte_perm(VL[r1], VL[r1 + STR], sel);
                mma3(acc[nt], a1h, a1l, bh, bl);
                // out2 B: qn c-packed from gmem
                uint2 q0 = __ldg(&qcb[(n0 + 8 * nt + g) * 32 + tq + kw]);
                uint2 q1 = __ldg(&qcb[(n0 + 8 * nt + g) * 32 + tq + 4 + kw]);
                bh[0] = q0.x; bh[1] = q1.x; bl[0] = q0.y; bl[1] = q1.y;
                mma3(acc[nt], a2h, a2l, bh, bl);
            }
        }
        // Epilogue: pair adjacent-c rows across lanes (lane^4 = g parity) and
        // store packed OC[p][cw] directly (OC overlays dead KN region).
        const bool evn = ((g & 1) == 0);
#pragma unroll
        for (int nt = 0; nt < 4; nt++) {
            float pv0 = __shfl_xor_sync(FULL, acc[nt][0], 4);
            float pv1 = __shfl_xor_sync(FULL, acc[nt][1], 4);
            float pv2 = __shfl_xor_sync(FULL, acc[nt][2], 4);
            float pv3 = __shfl_xor_sync(FULL, acc[nt][3], 4);
            int c = n0 + 8 * nt + 2 * tq;
            uint2 w0, w1;
            int cw;
            if (evn) {
                w0 = split_pair(acc[nt][0], pv0);   // rows (m0+g, m0+g+1), col c
                w1 = split_pair(acc[nt][1], pv1);   // col c+1
                cw = (m0 + g) >> 1;
            } else {
                w0 = split_pair(pv2, acc[nt][2]);   // rows (m0+g+7, m0+g+8), col c
                w1 = split_pair(pv3, acc[nt][3]);   // col c+1
                cw = (m0 + g + 7) >> 1;
            }
            OCH[c * STR + cw] = w0.x;
            OCL[c * STR + cw] = w0.y;
            OCH[(c + 1) * STR + cw] = w1.x;
            OCL[(c + 1) * STR + cw] = w1.y;
        }
    }
    __syncthreads();

    // ---- P6: proj y = PW @ O -> gmem (roll +4), float2 stores ----
    {
        const int m0 = (wid & 3) * 16;
        const int n0 = (wid >> 2) * 32;
        float acc[4][4];
#pragma unroll
        for (int i = 0; i < 4; i++)
#pragma unroll
            for (int j = 0; j < 4; j++) acc[i][j] = 0.f;
#pragma unroll
        for (int s = 0; s < 4; s++) {
            int kw = 8 * s;
            uint2 a0 = __ldg(&g_pwp[(m0 + g) * 32 + tq + kw]);
            uint2 a1 = __ldg(&g_pwp[(m0 + g + 8) * 32 + tq + kw]);
            uint2 a2 = __ldg(&g_pwp[(m0 + g) * 32 + tq + 4 + kw]);
            uint2 a3 = __ldg(&g_pwp[(m0 + g + 8) * 32 + tq + 4 + kw]);
            unsigned ah[4] = {a0.x, a1.x, a2.x, a3.x};
            unsigned al[4] = {a0.y, a1.y, a2.y, a3.y};
#pragma unroll
            for (int nt = 0; nt < 4; nt++) {
                int rb = (n0 + 8 * nt + g) * STR + tq + kw;
                unsigned bh[2] = {OCH[rb], OCH[rb + 4]};
                unsigned bl[2] = {OCL[rb], OCL[rb + 4]};
                mma3(acc[nt], ah, al, bh, bl);
            }
        }
        float* ob = out + (size_t)b * 64 * HH * WW_;
#pragma unroll
        for (int nt = 0; nt < 4; nt++) {
            int c = n0 + 8 * nt + 2 * tq;
            int pi = c >> 3;                        // pj = 2tq (pair stays in-row)
            int gh = (wh * 8 + pi + SHIFT) & 255;
            int gw = (ww * 8 + (c & 7) + SHIFT) & 255;
#pragma unroll
            for (int ri = 0; ri < 2; ri++) {
                int r = (m0 + g) + ri * 8;
                *(float2*)&ob[(size_t)r * HH * WW_ + (size_t)gh * WW_ + gw] =
                    make_float2(acc[nt][ri * 2], acc[nt][ri * 2 + 1]);
            }
        }
    }
}

extern "C" void kernel_launch(void* const* d_in, const int* in_sizes, int n_in,
                              void* d_out, int out_size) {
    const float* x      = (const float*)d_in[0];
    const float* q      = (const float*)d_in[1];
    const float* kv_w   = (const float*)d_in[2];
    const float* dw_w   = (const float*)d_in[3];
    const float* proj_w = (const float*)d_in[4];
    const float* rs1    = (const float*)d_in[5];
    const float* rs2    = (const float*)d_in[6];
    float* out = (float*)d_out;

    static bool attr_set = false;
    const int smem_bytes = 18432 * 4;  // 73,728 B
    if (!attr_set) {
        cudaFuncSetAttribute(win_kernel,
                             cudaFuncAttributeMaxDynamicSharedMemorySize,
                             smem_bytes);
        attr_set = true;
    }

    prep_q<<<64, 256>>>(q);
    prep_rest<<<16, 256>>>(kv_w, proj_w);
    win_kernel<<<8192, 256, smem_bytes>>>(x, dw_w, rs1, rs2, out);
}

// round 6
// speedup vs baseline: 3.5901x; 1.0925x over previous
#include <cuda_runtime.h>
#include <math.h>

#define HH 256
#define WW_ 256
#define SHIFT 4
#define STR 36   // packed smem row stride (u32 words); 144 B rows

// Pre-split constants in gmem: uint2 = (bf16x2 hi-pair, bf16x2 lo-pair), pairs along k
__device__ uint2 g_w2p[128 * 32];      // kv_w [oc][c-pair]
__device__ uint2 g_pwp[64 * 32];       // proj_w [oc][c-pair]
__device__ uint2 g_qp[8 * 64 * 32];    // qn [b][c][p-pair]   (k = p)
__device__ uint2 g_qc[8 * 64 * 32];    // qn [b][p][c-pair]   (k = c)
__device__ float g_qnf[8 * 64 * 64];

__device__ __forceinline__ unsigned pack_bf2(float v0, float v1) {
    unsigned d;
    asm("cvt.rn.bf16x2.f32 %0, %1, %2;" : "=r"(d) : "f"(v1), "f"(v0));  // lo16=v0, hi16=v1
    return d;
}
__device__ __forceinline__ uint2 split_pair(float v0, float v1) {
    unsigned h = pack_bf2(v0, v1);
    float h0 = __uint_as_float(h << 16);
    float h1 = __uint_as_float(h & 0xffff0000u);
    return make_uint2(h, pack_bf2(v0 - h0, v1 - h1));
}

// One warp per (b,c) row: l2-normalize q, emit g_qnf + g_qp.
__global__ void prep_q(const float* __restrict__ q) {
    int warp = (blockIdx.x * blockDim.x + threadIdx.x) >> 5;
    int lane = threadIdx.x & 31;
    if (warp >= 512) return;
    const float* qr = q + warp * 64;
    float v0 = qr[2 * lane], v1 = qr[2 * lane + 1];
    float ss = v0 * v0 + v1 * v1;
#pragma unroll
    for (int o = 16; o; o >>= 1) ss += __shfl_xor_sync(0xffffffffu, ss, o);
    float inv = 1.f / fmaxf(sqrtf(ss), 1e-12f);
    v0 *= inv; v1 *= inv;
    g_qnf[warp * 64 + 2 * lane] = v0;
    g_qnf[warp * 64 + 2 * lane + 1] = v1;
    g_qp[warp * 32 + lane] = split_pair(v0, v1);
}

// Wide: build w2p, pwp, qc (qc reads g_qnf written by prep_q).
__global__ void prep_rest(const float* __restrict__ kv_w,
                          const float* __restrict__ proj_w) {
    int gt = blockIdx.x * blockDim.x + threadIdx.x;  // 4096 threads
    if (gt < 4096) {
        int oc = gt >> 5, cw = gt & 31;
        g_w2p[gt] = split_pair(kv_w[oc * 64 + 2 * cw], kv_w[oc * 64 + 2 * cw + 1]);
    }
    if (gt < 2048) {
        int oc = gt >> 5, cw = gt & 31;
        g_pwp[gt] = split_pair(proj_w[oc * 64 + 2 * cw], proj_w[oc * 64 + 2 * cw + 1]);
    }
    for (int idx = gt; idx < 16384; idx += 4096) {
        int b = idx >> 11, rem = idx & 2047;
        int p = rem >> 5, cw = rem & 31;
        float v0 = g_qnf[(b * 64 + 2 * cw) * 64 + p];
        float v1 = g_qnf[(b * 64 + 2 * cw + 1) * 64 + p];
        g_qc[idx] = split_pair(v0, v1);
    }
}

__device__ __forceinline__ void mma16(float (&d)[4], const unsigned (&a)[4], const unsigned (&b)[2]) {
    asm("mma.sync.aligned.m16n8k16.row.col.f32.bf16.bf16.f32 "
        "{%0,%1,%2,%3}, {%4,%5,%6,%7}, {%8,%9}, {%0,%1,%2,%3};"
        : "+f"(d[0]), "+f"(d[1]), "+f"(d[2]), "+f"(d[3])
        : "r"(a[0]), "r"(a[1]), "r"(a[2]), "r"(a[3]), "r"(b[0]), "r"(b[1]));
}
__device__ __forceinline__ void mma3(float (&d)[4], const unsigned (&ah)[4], const unsigned (&al)[4],
                                     const unsigned (&bh)[2], const unsigned (&bl)[2]) {
    mma16(d, al, bh);
    mma16(d, ah, bl);
    mma16(d, ah, bh);
}

__device__ __forceinline__ unsigned sptr(const void* p) {
    return (unsigned)__cvta_generic_to_shared(p);
}
__device__ __forceinline__ void ldsm4(unsigned (&r)[4], unsigned addr) {
    asm volatile("ldmatrix.sync.aligned.m8n8.x4.shared.b16 {%0,%1,%2,%3}, [%4];"
        : "=r"(r[0]), "=r"(r[1]), "=r"(r[2]), "=r"(r[3]) : "r"(addr));
}
__device__ __forceinline__ void ldsm4t(unsigned (&r)[4], unsigned addr) {
    asm volatile("ldmatrix.sync.aligned.m8n8.x4.trans.shared.b16 {%0,%1,%2,%3}, [%4];"
        : "=r"(r[0]), "=r"(r[1]), "=r"(r[2]), "=r"(r[3]) : "r"(addr));
}

// smem u32 layout (total 18432 u32 = 73728 B):
//  [0,4608)      XC_H/XC_L  -> A1_H/A1_L
//  [4608,9216)   KN_H/KN_L  -> OC_H/OC_L (packed O, written in P4 epilogue)
//  [9216,13824)  V_H/V_L
//  [13824,18432) A2_H/A2_L
__global__ __launch_bounds__(256, 3) void win_kernel(
    const float* __restrict__ x,
    const float* __restrict__ dw_w,
    const float* __restrict__ rs1,
    const float* __restrict__ rs2,
    float* __restrict__ out)
{
    extern __shared__ unsigned su[];
    unsigned* XH = su;
    unsigned* XL = su + 2304;
    unsigned* A1H = su;            // after P3
    unsigned* A1L = su + 2304;
    unsigned* KNH = su + 4608;
    unsigned* KNL = su + 6912;
    unsigned* OCH = su + 4608;     // after P4 (KN dead)
    unsigned* OCL = su + 6912;
    unsigned* VH  = su + 9216;
    unsigned* VL  = su + 11520;
    unsigned* A2H = su + 13824;
    unsigned* A2L = su + 16128;

    const int tid  = threadIdx.x;
    const int wid  = tid >> 5;
    const int lane = tid & 31;
    const int g = lane >> 2, tq = lane & 3;
    const unsigned FULL = 0xffffffffu;

    // ldmatrix per-lane address components
    const int rr  = lane & 7;
    const int bB  = (lane >> 3) & 1;   // B: k-half (non-trans) / k-half (trans)
    const int bA  = (lane >> 4) & 1;   // A: k-half
    const int ntl = (lane >> 4) & 1;   // B: n-tile within pair
    const int rhA = (lane >> 3) & 1;   // A: row-half

    const int bw = blockIdx.x;
    const int b  = bw >> 10;
    const int w  = bw & 1023;
    const int wh = w >> 5, ww = w & 31;
    const float r1v = rs1[0], r2v = rs2[0];
    const uint2* __restrict__ qpb = g_qp + b * 2048;
    const uint2* __restrict__ qcb = g_qc + b * 2048;

    // ---- P0: load X window (roll -4), pack pairs along c -> XC[p][cw] ----
    const float* xb = x + (size_t)b * 64 * HH * WW_;
    for (int idx = tid; idx < 2048; idx += 256) {
        int p = idx & 63, cw = idx >> 6;
        int gh = (wh * 8 + (p >> 3) + SHIFT) & 255;
        int gw = (ww * 8 + (p & 7) + SHIFT) & 255;
        size_t off = (size_t)gh * WW_ + gw;
        float v0 = xb[(size_t)(2 * cw) * HH * WW_ + off];
        float v1 = xb[(size_t)(2 * cw + 1) * HH * WW_ + off];
        uint2 pr = split_pair(v0, v1);
        XH[p * STR + cw] = pr.x;
        XL[p * STR + cw] = pr.y;
    }
    __syncthreads();

    // ---- P2: conv1x1 (regs) + in-register dwconv + norm + pack KN/V ----
    {
        const int m0 = wid * 16;
        float acc[8][4];
#pragma unroll
        for (int i = 0; i < 8; i++)
#pragma unroll
            for (int j = 0; j < 4; j++) acc[i][j] = 0.f;
        const unsigned xh0 = sptr(XH), xl0 = sptr(XL);
#pragma unroll
        for (int s = 0; s < 4; s++) {
            int kw = 8 * s;
            uint2 a0 = __ldg(&g_w2p[(m0 + g) * 32 + tq + kw]);
            uint2 a1 = __ldg(&g_w2p[(m0 + g + 8) * 32 + tq + kw]);
            uint2 a2 = __ldg(&g_w2p[(m0 + g) * 32 + tq + 4 + kw]);
            uint2 a3 = __ldg(&g_w2p[(m0 + g + 8) * 32 + tq + 4 + kw]);
            unsigned ah[4] = {a0.x, a1.x, a2.x, a3.x};
            unsigned al[4] = {a0.y, a1.y, a2.y, a3.y};
#pragma unroll
            for (int np = 0; np < 4; np++) {
                unsigned ro = ((np * 2 + ntl) * 8 + rr) * 144 + bB * 16 + s * 32;
                unsigned bhr[4], blr[4];
                ldsm4(bhr, xh0 + ro);
                ldsm4(blr, xl0 + ro);
                unsigned bh0[2] = {bhr[0], bhr[1]}, bl0[2] = {blr[0], blr[1]};
                unsigned bh1[2] = {bhr[2], bhr[3]}, bl1[2] = {blr[2], blr[3]};
                mma3(acc[np * 2],     ah, al, bh0, bl0);
                mma3(acc[np * 2 + 1], ah, al, bh1, bl1);
            }
        }
        // dwconv per m-half
#pragma unroll
        for (int h = 0; h < 2; h++) {
            const int oc = m0 + 8 * h + g;
            float wv[9];
#pragma unroll
            for (int q9 = 0; q9 < 9; q9++) wv[q9] = __ldg(&dw_w[oc * 9 + q9]);
            float o0[8], o1[8];
#pragma unroll
            for (int i = 0; i < 8; i++) { o0[i] = 0.f; o1[i] = 0.f; }
#pragma unroll
            for (int ii = 0; ii < 8; ii++) {
                float c0 = acc[ii][2 * h], c1 = acc[ii][2 * h + 1];
                float Lv = __shfl_up_sync(FULL, c1, 1);
                float Rv = __shfl_down_sync(FULL, c0, 1);
                if (tq == 0) Lv = 0.f;
                if (tq == 3) Rv = 0.f;
#pragma unroll
                for (int dy = 0; dy < 3; dy++) {
                    int i = ii + 1 - dy;
                    if (i < 0 || i > 7) continue;
                    o0[i] = fmaf(wv[dy * 3 + 0], Lv, fmaf(wv[dy * 3 + 1], c0, fmaf(wv[dy * 3 + 2], c1, o0[i])));
                    o1[i] = fmaf(wv[dy * 3 + 0], c0, fmaf(wv[dy * 3 + 1], c1, fmaf(wv[dy * 3 + 2], Rv, o1[i])));
                }
            }
            unsigned* DH; unsigned* DL; int row;
            if (wid < 4) {   // K: l2-normalize rows
                float ss = 0.f;
#pragma unroll
                for (int i = 0; i < 8; i++) ss += o0[i] * o0[i] + o1[i] * o1[i];
                ss += __shfl_xor_sync(FULL, ss, 1);
                ss += __shfl_xor_sync(FULL, ss, 2);
                float inv = 1.f / fmaxf(sqrtf(ss), 1e-12f);
#pragma unroll
                for (int i = 0; i < 8; i++) { o0[i] *= inv; o1[i] *= inv; }
                DH = KNH; DL = KNL; row = oc;
            } else {
                DH = VH; DL = VL; row = oc - 64;
            }
#pragma unroll
            for (int i = 0; i < 8; i++) {
                uint2 pr = split_pair(o0[i], o1[i]);
                DH[row * STR + 4 * i + tq] = pr.x;
                DL[row * STR + 4 * i + tq] = pr.y;
            }
        }
    }
    __syncthreads();

    // ---- P3: S-GEMM (S1 or S2 per warp) + in-register softmax + pack A ----
    {
        const int mat = wid >> 2;
        const int m0 = (wid & 3) * 16;
        const float rv = mat ? r2v : r1v;
        float acc[8][4];
#pragma unroll
        for (int i = 0; i < 8; i++)
#pragma unroll
            for (int j = 0; j < 4; j++) acc[i][j] = 0.f;
        const unsigned knh0 = sptr(KNH), knl0 = sptr(KNL);
        const unsigned vh0 = sptr(VH), vl0 = sptr(VL);
        const unsigned aoffb = (m0 + rhA * 8 + rr) * 144 + bA * 16;
#pragma unroll
        for (int s = 0; s < 4; s++) {
            int kw = 8 * s;
            unsigned ah[4], al[4];
            ldsm4(ah, knh0 + aoffb + s * 32);
            ldsm4(al, knl0 + aoffb + s * 32);
            if (mat == 0) {
#pragma unroll
                for (int nt = 0; nt < 8; nt++) {
                    uint2 q0 = __ldg(&qpb[(8 * nt + g) * 32 + tq + kw]);
                    uint2 q1 = __ldg(&qpb[(8 * nt + g) * 32 + tq + 4 + kw]);
                    unsigned bh[2] = {q0.x, q1.x}, bl[2] = {q0.y, q1.y};
                    mma3(acc[nt], ah, al, bh, bl);
                }
            } else {
#pragma unroll
                for (int np = 0; np < 4; np++) {
                    unsigned ro = ((np * 2 + ntl) * 8 + rr) * 144 + bB * 16 + s * 32;
                    unsigned bhr[4], blr[4];
                    ldsm4(bhr, vh0 + ro);
                    ldsm4(blr, vl0 + ro);
                    unsigned bh0[2] = {bhr[0], bhr[1]}, bl0[2] = {blr[0], blr[1]};
                    unsigned bh1[2] = {bhr[2], bhr[3]}, bl1[2] = {blr[2], blr[3]};
                    mma3(acc[np * 2],     ah, al, bh0, bl0);
                    mma3(acc[np * 2 + 1], ah, al, bh1, bl1);
                }
            }
        }
        unsigned* DH = mat ? A2H : A1H;
        unsigned* DL = mat ? A2L : A1L;
#pragma unroll
        for (int h = 0; h < 2; h++) {
            float m = -1e30f;
#pragma unroll
            for (int nt = 0; nt < 8; nt++) {
                acc[nt][2 * h] *= rv; acc[nt][2 * h + 1] *= rv;
                m = fmaxf(m, fmaxf(acc[nt][2 * h], acc[nt][2 * h + 1]));
            }
            m = fmaxf(m, __shfl_xor_sync(FULL, m, 1));
            m = fmaxf(m, __shfl_xor_sync(FULL, m, 2));
            float s = 0.f;
            float e[16];
#pragma unroll
            for (int nt = 0; nt < 8; nt++) {
                e[2 * nt]     = __expf(acc[nt][2 * h] - m);
                e[2 * nt + 1] = __expf(acc[nt][2 * h + 1] - m);
                s += e[2 * nt] + e[2 * nt + 1];
            }
            s += __shfl_xor_sync(FULL, s, 1);
            s += __shfl_xor_sync(FULL, s, 2);
            float inv = 1.f / s;
            int row = m0 + g + 8 * h;
#pragma unroll
            for (int nt = 0; nt < 8; nt++) {
                uint2 pr = split_pair(e[2 * nt] * inv, e[2 * nt + 1] * inv);
                DH[row * STR + 4 * nt + tq] = pr.x;
                DL[row * STR + 4 * nt + tq] = pr.y;
            }
        }
    }
    __syncthreads();

    // ---- P4: out = A1@V + A2@Qn; epilogue packs O pairs-along-c via shfl -> OC ----
    {
        const int m0 = (wid & 3) * 16;
        const int n0 = (wid >> 2) * 32;
        float acc[4][4];
#pragma unroll
        for (int i = 0; i < 4; i++)
#pragma unroll
            for (int j = 0; j < 4; j++) acc[i][j] = 0.f;
        const unsigned a1h0 = sptr(A1H), a1l0 = sptr(A1L);
        const unsigned a2h0 = sptr(A2H), a2l0 = sptr(A2L);
        const unsigned vh0 = sptr(VH), vl0 = sptr(VL);
        const unsigned aoffb = (m0 + rhA * 8 + rr) * 144 + bA * 16;
#pragma unroll
        for (int s = 0; s < 4; s++) {
            int kw = 8 * s;
            unsigned a1h[4], a1l[4], a2h[4], a2l[4];
            ldsm4(a1h, a1h0 + aoffb + s * 32);
            ldsm4(a1l, a1l0 + aoffb + s * 32);
            ldsm4(a2h, a2h0 + aoffb + s * 32);
            ldsm4(a2l, a2l0 + aoffb + s * 32);
#pragma unroll
            for (int np = 0; np < 2; np++) {
                // out1 B: V^T via ldmatrix.trans (rows = k = channel, cols = p)
                unsigned vo = (16 * s + bB * 8 + rr) * 144 + (n0 + (np * 2 + ntl) * 8) * 2;
                unsigned bhr[4], blr[4];
                ldsm4t(bhr, vh0 + vo);
                ldsm4t(blr, vl0 + vo);
                unsigned bh0[2] = {bhr[0], bhr[1]}, bl0[2] = {blr[0], blr[1]};
                unsigned bh1[2] = {bhr[2], bhr[3]}, bl1[2] = {blr[2], blr[3]};
                mma3(acc[np * 2],     a1h, a1l, bh0, bl0);
                mma3(acc[np * 2 + 1], a1h, a1l, bh1, bl1);
                // out2 B: qn c-packed from gmem
#pragma unroll
                for (int half = 0; half < 2; half++) {
                    int nt = np * 2 + half;
                    uint2 q0 = __ldg(&qcb[(n0 + 8 * nt + g) * 32 + tq + kw]);
                    uint2 q1 = __ldg(&qcb[(n0 + 8 * nt + g) * 32 + tq + 4 + kw]);
                    unsigned bh[2] = {q0.x, q1.x}, bl[2] = {q0.y, q1.y};
                    mma3(acc[nt], a2h, a2l, bh, bl);
                }
            }
        }
        // Epilogue: pair adjacent-c rows across lanes (lane^4 = g parity) and
        // store packed OC[p][cw] directly (OC overlays dead KN region).
        const bool evn = ((g & 1) == 0);
#pragma unroll
        for (int nt = 0; nt < 4; nt++) {
            float pv0 = __shfl_xor_sync(FULL, acc[nt][0], 4);
            float pv1 = __shfl_xor_sync(FULL, acc[nt][1], 4);
            float pv2 = __shfl_xor_sync(FULL, acc[nt][2], 4);
            float pv3 = __shfl_xor_sync(FULL, acc[nt][3], 4);
            int c = n0 + 8 * nt + 2 * tq;
            uint2 w0, w1;
            int cw;
            if (evn) {
                w0 = split_pair(acc[nt][0], pv0);   // rows (m0+g, m0+g+1), col c
                w1 = split_pair(acc[nt][1], pv1);   // col c+1
                cw = (m0 + g) >> 1;
            } else {
                w0 = split_pair(pv2, acc[nt][2]);   // rows (m0+g+7, m0+g+8), col c
                w1 = split_pair(pv3, acc[nt][3]);   // col c+1
                cw = (m0 + g + 7) >> 1;
            }
            OCH[c * STR + cw] = w0.x;
            OCL[c * STR + cw] = w0.y;
            OCH[(c + 1) * STR + cw] = w1.x;
            OCL[(c + 1) * STR + cw] = w1.y;
        }
    }
    __syncthreads();

    // ---- P6: proj y = PW @ O -> gmem (roll +4), float2 stores ----
    {
        const int m0 = (wid & 3) * 16;
        const int n0 = (wid >> 2) * 32;
        float acc[4][4];
#pragma unroll
        for (int i = 0; i < 4; i++)
#pragma unroll
            for (int j = 0; j < 4; j++) acc[i][j] = 0.f;
        const unsigned och0 = sptr(OCH), ocl0 = sptr(OCL);
#pragma unroll
        for (int s = 0; s < 4; s++) {
            int kw = 8 * s;
            uint2 a0 = __ldg(&g_pwp[(m0 + g) * 32 + tq + kw]);
            uint2 a1 = __ldg(&g_pwp[(m0 + g + 8) * 32 + tq + kw]);
            uint2 a2 = __ldg(&g_pwp[(m0 + g) * 32 + tq + 4 + kw]);
            uint2 a3 = __ldg(&g_pwp[(m0 + g + 8) * 32 + tq + 4 + kw]);
            unsigned ah[4] = {a0.x, a1.x, a2.x, a3.x};
            unsigned al[4] = {a0.y, a1.y, a2.y, a3.y};
#pragma unroll
            for (int np = 0; np < 2; np++) {
                unsigned ro = (n0 + (np * 2 + ntl) * 8 + rr) * 144 + bB * 16 + s * 32;
                unsigned bhr[4], blr[4];
                ldsm4(bhr, och0 + ro);
                ldsm4(blr, ocl0 + ro);
                unsigned bh0[2] = {bhr[0], bhr[1]}, bl0[2] = {blr[0], blr[1]};
                unsigned bh1[2] = {bhr[2], bhr[3]}, bl1[2] = {blr[2], blr[3]};
                mma3(acc[np * 2],     ah, al, bh0, bl0);
                mma3(acc[np * 2 + 1], ah, al, bh1, bl1);
            }
        }
        float* ob = out + (size_t)b * 64 * HH * WW_;
#pragma unroll
        for (int nt = 0; nt < 4; nt++) {
            int c = n0 + 8 * nt + 2 * tq;
            int pi = c >> 3;                        // pj = 2tq (pair stays in-row)
            int gh = (wh * 8 + pi + SHIFT) & 255;
            int gw = (ww * 8 + (c & 7) + SHIFT) & 255;
#pragma unroll
            for (int ri = 0; ri < 2; ri++) {
                int r = (m0 + g) + ri * 8;
                *(float2*)&ob[(size_t)r * HH * WW_ + (size_t)gh * WW_ + gw] =
                    make_float2(acc[nt][ri * 2], acc[nt][ri * 2 + 1]);
            }
        }
    }
}

extern "C" void kernel_launch(void* const* d_in, const int* in_sizes, int n_in,
                              void* d_out, int out_size) {
    const float* x      = (const float*)d_in[0];
    const float* q      = (const float*)d_in[1];
    const float* kv_w   = (const float*)d_in[2];
    const float* dw_w   = (const float*)d_in[3];
    const float* proj_w = (const float*)d_in[4];
    const float* rs1    = (const float*)d_in[5];
    const float* rs2    = (const float*)d_in[6];
    float* out = (float*)d_out;

    static bool attr_set = false;
    const int smem_bytes = 18432 * 4;  // 73,728 B
    if (!attr_set) {
        cudaFuncSetAttribute(win_kernel,
                             cudaFuncAttributeMaxDynamicSharedMemorySize,
                             smem_bytes);
        attr_set = true;
    }

    prep_q<<<64, 256>>>(q);
    prep_rest<<<16, 256>>>(kv_w, proj_w);
    win_kernel<<<8192, 256, smem_bytes>>>(x, dw_w, rs1, rs2, out);
}

// round 7
// speedup vs baseline: 4.4241x; 1.2323x over previous
#include <cuda_runtime.h>
#include <math.h>

#define HH 256
#define WW_ 256
#define SHIFT 4
#define STR 36   // packed smem row stride (u32 words); 144 B rows

// Fragment-order pre-split tables.
// A-records (2 uint4 per lane per k16-chunk):
//   rec = (((mb*4 + s)*8 + g)*4 + tq)*2 + half
//   uint4 = (hi(r0,w), lo(r0,w), hi(r1,w), lo(r1,w)); r0=mb*16+g, r1=r0+8, w=8s+tq+4*half
// B-records (1 uint4 per lane per n-tile per k16-chunk):
//   rec = ((nt*4 + s)*8 + g)*4 + tq
//   uint4 = (hi(n,w0), lo(n,w0), hi(n,w1), lo(n,w1)); n=nt*8+g, w0=8s+tq, w1=w0+4
__device__ uint4 g_w2f[2048];        // kv_w  A-order (128 rows)
__device__ uint4 g_pwf[1024];        // proj_w A-order (64 rows)
__device__ uint4 g_qpf[8 * 1024];    // qn [b], rows=c, k=p   B-order
__device__ uint4 g_qcf[8 * 1024];    // qn [b], rows=p, k=c   B-order

__device__ __forceinline__ unsigned pack_bf2(float v0, float v1) {
    unsigned d;
    asm("cvt.rn.bf16x2.f32 %0, %1, %2;" : "=r"(d) : "f"(v1), "f"(v0));  // lo16=v0, hi16=v1
    return d;
}
__device__ __forceinline__ uint2 split_pair(float v0, float v1) {
    unsigned h = pack_bf2(v0, v1);
    float h0 = __uint_as_float(h << 16);
    float h1 = __uint_as_float(h & 0xffff0000u);
    return make_uint2(h, pack_bf2(v0 - h0, v1 - h1));
}

// Single prep launch: blocks 0-7 handle q (per-batch), 8-23 kv_w, 24-31 proj_w.
__global__ void prep(const float* __restrict__ q,
                     const float* __restrict__ kv_w,
                     const float* __restrict__ proj_w) {
    const int tid = threadIdx.x;
    if (blockIdx.x < 8) {
        const int b = blockIdx.x;
        __shared__ float qs[4096];
        __shared__ float innorm[64];
        for (int i = tid; i < 4096; i += 256) qs[i] = q[b * 4096 + i];
        __syncthreads();
        int wid = tid >> 5, lane = tid & 31;
        for (int r = wid; r < 64; r += 8) {
            float v0 = qs[r * 64 + lane], v1 = qs[r * 64 + 32 + lane];
            float ss = v0 * v0 + v1 * v1;
#pragma unroll
            for (int o = 16; o; o >>= 1) ss += __shfl_xor_sync(0xffffffffu, ss, o);
            if (lane == 0) innorm[r] = 1.f / fmaxf(sqrtf(ss), 1e-12f);
        }
        __syncthreads();
        for (int rec = tid; rec < 1024; rec += 256) {
            int tq = rec & 3, g = (rec >> 2) & 7, s = (rec >> 5) & 3, nt = rec >> 7;
            int row = nt * 8 + g;
            float inv = innorm[row];
            // qp: k = p, elements 16s+2tq (+1), +8 (+9)
            int e0 = 16 * s + 2 * tq;
            uint2 u0 = split_pair(qs[row * 64 + e0] * inv, qs[row * 64 + e0 + 1] * inv);
            uint2 u1 = split_pair(qs[row * 64 + e0 + 8] * inv, qs[row * 64 + e0 + 9] * inv);
            g_qpf[b * 1024 + rec] = make_uint4(u0.x, u0.y, u1.x, u1.y);
            // qc: rows = p (=row), k = c
            int c0 = 16 * s + 2 * tq;
            uint2 w0 = split_pair(qs[c0 * 64 + row] * innorm[c0],
                                  qs[(c0 + 1) * 64 + row] * innorm[c0 + 1]);
            uint2 w1 = split_pair(qs[(c0 + 8) * 64 + row] * innorm[c0 + 8],
                                  qs[(c0 + 9) * 64 + row] * innorm[c0 + 9]);
            g_qcf[b * 1024 + rec] = make_uint4(w0.x, w0.y, w1.x, w1.y);
        }
    } else if (blockIdx.x < 24) {
        int rec = (blockIdx.x - 8) * 256 + tid;   // < 4096, need 2048
        if (rec < 2048) {
            int half = rec & 1, tq = (rec >> 1) & 3, g = (rec >> 3) & 7;
            int s = (rec >> 6) & 3, mb = rec >> 8;
            int r0 = mb * 16 + g, r1 = r0 + 8;
            int e = 2 * (8 * s + tq + 4 * half);
            uint2 u0 = split_pair(kv_w[r0 * 64 + e], kv_w[r0 * 64 + e + 1]);
            uint2 u1 = split_pair(kv_w[r1 * 64 + e], kv_w[r1 * 64 + e + 1]);
            g_w2f[rec] = make_uint4(u0.x, u0.y, u1.x, u1.y);
        }
    } else {
        int rec = (blockIdx.x - 24) * 256 + tid;  // < 2048, need 1024
        if (rec < 1024) {
            int half = rec & 1, tq = (rec >> 1) & 3, g = (rec >> 3) & 7;
            int s = (rec >> 6) & 3, mb = rec >> 8;
            int r0 = mb * 16 + g, r1 = r0 + 8;
            int e = 2 * (8 * s + tq + 4 * half);
            uint2 u0 = split_pair(proj_w[r0 * 64 + e], proj_w[r0 * 64 + e + 1]);
            uint2 u1 = split_pair(proj_w[r1 * 64 + e], proj_w[r1 * 64 + e + 1]);
            g_pwf[rec] = make_uint4(u0.x, u0.y, u1.x, u1.y);
        }
    }
}

__device__ __forceinline__ void mma16(float (&d)[4], const unsigned (&a)[4], const unsigned (&b)[2]) {
    asm("mma.sync.aligned.m16n8k16.row.col.f32.bf16.bf16.f32 "
        "{%0,%1,%2,%3}, {%4,%5,%6,%7}, {%8,%9}, {%0,%1,%2,%3};"
        : "+f"(d[0]), "+f"(d[1]), "+f"(d[2]), "+f"(d[3])
        : "r"(a[0]), "r"(a[1]), "r"(a[2]), "r"(a[3]), "r"(b[0]), "r"(b[1]));
}
__device__ __forceinline__ void mma3(float (&d)[4], const unsigned (&ah)[4], const unsigned (&al)[4],
                                     const unsigned (&bh)[2], const unsigned (&bl)[2]) {
    mma16(d, al, bh);
    mma16(d, ah, bl);
    mma16(d, ah, bh);
}

__device__ __forceinline__ unsigned sptr(const void* p) {
    return (unsigned)__cvta_generic_to_shared(p);
}
__device__ __forceinline__ void ldsm4(unsigned (&r)[4], unsigned addr) {
    asm volatile("ldmatrix.sync.aligned.m8n8.x4.shared.b16 {%0,%1,%2,%3}, [%4];"
        : "=r"(r[0]), "=r"(r[1]), "=r"(r[2]), "=r"(r[3]) : "r"(addr));
}
__device__ __forceinline__ void ldsm4t(unsigned (&r)[4], unsigned addr) {
    asm volatile("ldmatrix.sync.aligned.m8n8.x4.trans.shared.b16 {%0,%1,%2,%3}, [%4];"
        : "=r"(r[0]), "=r"(r[1]), "=r"(r[2]), "=r"(r[3]) : "r"(addr));
}

// smem u32 layout (total 18432 u32 = 73728 B):
//  [0,4608)      XC_H/XC_L  -> A1_H/A1_L
//  [4608,9216)   KN_H/KN_L  -> OC_H/OC_L (packed O, written in P4 epilogue)
//  [9216,13824)  V_H/V_L
//  [13824,18432) A2_H/A2_L
__global__ __launch_bounds__(256, 3) void win_kernel(
    const float* __restrict__ x,
    const float* __restrict__ dw_w,
    const float* __restrict__ rs1,
    const float* __restrict__ rs2,
    float* __restrict__ out)
{
    extern __shared__ unsigned su[];
    unsigned* XH = su;
    unsigned* XL = su + 2304;
    unsigned* A1H = su;            // after P3
    unsigned* A1L = su + 2304;
    unsigned* KNH = su + 4608;
    unsigned* KNL = su + 6912;
    unsigned* OCH = su + 4608;     // after P4 (KN dead)
    unsigned* OCL = su + 6912;
    unsigned* VH  = su + 9216;
    unsigned* VL  = su + 11520;
    unsigned* A2H = su + 13824;
    unsigned* A2L = su + 16128;

    const int tid  = threadIdx.x;
    const int wid  = tid >> 5;
    const int lane = tid & 31;
    const int g = lane >> 2, tq = lane & 3;
    const unsigned FULL = 0xffffffffu;

    // ldmatrix per-lane address components
    const int rr  = lane & 7;
    const int bB  = (lane >> 3) & 1;   // B: k-half
    const int bA  = (lane >> 4) & 1;   // A: k-half
    const int ntl = (lane >> 4) & 1;   // B: n-tile within pair
    const int rhA = (lane >> 3) & 1;   // A: row-half

    const int bw = blockIdx.x;
    const int b  = bw >> 10;
    const int w  = bw & 1023;
    const int wh = w >> 5, ww = w & 31;
    const float r1v = rs1[0], r2v = rs2[0];
    const uint4* __restrict__ qpb = g_qpf + b * 1024;
    const uint4* __restrict__ qcb = g_qcf + b * 1024;

    // ---- P0: load X window (roll -4), pack pairs along c -> XC[p][cw] ----
    const float* xb = x + (size_t)b * 64 * HH * WW_;
    for (int idx = tid; idx < 2048; idx += 256) {
        int p = idx & 63, cw = idx >> 6;
        int gh = (wh * 8 + (p >> 3) + SHIFT) & 255;
        int gw = (ww * 8 + (p & 7) + SHIFT) & 255;
        size_t off = (size_t)gh * WW_ + gw;
        float v0 = xb[(size_t)(2 * cw) * HH * WW_ + off];
        float v1 = xb[(size_t)(2 * cw + 1) * HH * WW_ + off];
        uint2 pr = split_pair(v0, v1);
        XH[p * STR + cw] = pr.x;
        XL[p * STR + cw] = pr.y;
    }
    __syncthreads();

    // ---- P2: conv1x1 (regs) + in-register dwconv + norm + pack KN/V ----
    {
        const int m0 = wid * 16;
        float acc[8][4];
#pragma unroll
        for (int i = 0; i < 8; i++)
#pragma unroll
            for (int j = 0; j < 4; j++) acc[i][j] = 0.f;
        const unsigned xh0 = sptr(XH), xl0 = sptr(XL);
#pragma unroll
        for (int s = 0; s < 4; s++) {
            int recA = (((wid * 4 + s) * 8 + g) * 4 + tq) * 2;
            uint4 A0 = __ldg(&g_w2f[recA]);
            uint4 A1v = __ldg(&g_w2f[recA + 1]);
            unsigned ah[4] = {A0.x, A0.z, A1v.x, A1v.z};
            unsigned al[4] = {A0.y, A0.w, A1v.y, A1v.w};
#pragma unroll
            for (int np = 0; np < 4; np++) {
                unsigned ro = ((np * 2 + ntl) * 8 + rr) * 144 + bB * 16 + s * 32;
                unsigned bhr[4], blr[4];
                ldsm4(bhr, xh0 + ro);
                ldsm4(blr, xl0 + ro);
                unsigned bh0[2] = {bhr[0], bhr[1]}, bl0[2] = {blr[0], blr[1]};
                unsigned bh1[2] = {bhr[2], bhr[3]}, bl1[2] = {blr[2], blr[3]};
                mma3(acc[np * 2],     ah, al, bh0, bl0);
                mma3(acc[np * 2 + 1], ah, al, bh1, bl1);
            }
        }
        // dwconv per m-half
#pragma unroll
        for (int h = 0; h < 2; h++) {
            const int oc = m0 + 8 * h + g;
            float wv[9];
#pragma unroll
            for (int q9 = 0; q9 < 9; q9++) wv[q9] = __ldg(&dw_w[oc * 9 + q9]);
            float o0[8], o1[8];
#pragma unroll
            for (int i = 0; i < 8; i++) { o0[i] = 0.f; o1[i] = 0.f; }
#pragma unroll
            for (int ii = 0; ii < 8; ii++) {
                float c0 = acc[ii][2 * h], c1 = acc[ii][2 * h + 1];
                float Lv = __shfl_up_sync(FULL, c1, 1);
                float Rv = __shfl_down_sync(FULL, c0, 1);
                if (tq == 0) Lv = 0.f;
                if (tq == 3) Rv = 0.f;
#pragma unroll
                for (int dy = 0; dy < 3; dy++) {
                    int i = ii + 1 - dy;
                    if (i < 0 || i > 7) continue;
                    o0[i] = fmaf(wv[dy * 3 + 0], Lv, fmaf(wv[dy * 3 + 1], c0, fmaf(wv[dy * 3 + 2], c1, o0[i])));
                    o1[i] = fmaf(wv[dy * 3 + 0], c0, fmaf(wv[dy * 3 + 1], c1, fmaf(wv[dy * 3 + 2], Rv, o1[i])));
                }
            }
            unsigned* DH; unsigned* DL; int row;
            if (wid < 4) {   // K: l2-normalize rows
                float ss = 0.f;
#pragma unroll
                for (int i = 0; i < 8; i++) ss += o0[i] * o0[i] + o1[i] * o1[i];
                ss += __shfl_xor_sync(FULL, ss, 1);
                ss += __shfl_xor_sync(FULL, ss, 2);
                float inv = 1.f / fmaxf(sqrtf(ss), 1e-12f);
#pragma unroll
                for (int i = 0; i < 8; i++) { o0[i] *= inv; o1[i] *= inv; }
                DH = KNH; DL = KNL; row = oc;
            } else {
                DH = VH; DL = VL; row = oc - 64;
            }
#pragma unroll
            for (int i = 0; i < 8; i++) {
                uint2 pr = split_pair(o0[i], o1[i]);
                DH[row * STR + 4 * i + tq] = pr.x;
                DL[row * STR + 4 * i + tq] = pr.y;
            }
        }
    }
    __syncthreads();

    // ---- P3: S-GEMM (S1 or S2 per warp) + in-register softmax + pack A ----
    {
        const int mat = wid >> 2;
        const int m0 = (wid & 3) * 16;
        const float rv = mat ? r2v : r1v;
        float acc[8][4];
#pragma unroll
        for (int i = 0; i < 8; i++)
#pragma unroll
            for (int j = 0; j < 4; j++) acc[i][j] = 0.f;
        const unsigned knh0 = sptr(KNH), knl0 = sptr(KNL);
        const unsigned vh0 = sptr(VH), vl0 = sptr(VL);
        const unsigned aoffb = (m0 + rhA * 8 + rr) * 144 + bA * 16;
#pragma unroll
        for (int s = 0; s < 4; s++) {
            unsigned ah[4], al[4];
            ldsm4(ah, knh0 + aoffb + s * 32);
            ldsm4(al, knl0 + aoffb + s * 32);
            if (mat == 0) {
#pragma unroll
                for (int nt = 0; nt < 8; nt++) {
                    uint4 Q = __ldg(&qpb[((nt * 4 + s) * 8 + g) * 4 + tq]);
                    unsigned bh[2] = {Q.x, Q.z}, bl[2] = {Q.y, Q.w};
                    mma3(acc[nt], ah, al, bh, bl);
                }
            } else {
#pragma unroll
                for (int np = 0; np < 4; np++) {
                    unsigned ro = ((np * 2 + ntl) * 8 + rr) * 144 + bB * 16 + s * 32;
                    unsigned bhr[4], blr[4];
                    ldsm4(bhr, vh0 + ro);
                    ldsm4(blr, vl0 + ro);
                    unsigned bh0[2] = {bhr[0], bhr[1]}, bl0[2] = {blr[0], blr[1]};
                    unsigned bh1[2] = {bhr[2], bhr[3]}, bl1[2] = {blr[2], blr[3]};
                    mma3(acc[np * 2],     ah, al, bh0, bl0);
                    mma3(acc[np * 2 + 1], ah, al, bh1, bl1);
                }
            }
        }
        unsigned* DH = mat ? A2H : A1H;
        unsigned* DL = mat ? A2L : A1L;
#pragma unroll
        for (int h = 0; h < 2; h++) {
            float m = -1e30f;
#pragma unroll
            for (int nt = 0; nt < 8; nt++) {
                acc[nt][2 * h] *= rv; acc[nt][2 * h + 1] *= rv;
                m = fmaxf(m, fmaxf(acc[nt][2 * h], acc[nt][2 * h + 1]));
            }
            m = fmaxf(m, __shfl_xor_sync(FULL, m, 1));
            m = fmaxf(m, __shfl_xor_sync(FULL, m, 2));
            float s = 0.f;
            float e[16];
#pragma unroll
            for (int nt = 0; nt < 8; nt++) {
                e[2 * nt]     = __expf(acc[nt][2 * h] - m);
                e[2 * nt + 1] = __expf(acc[nt][2 * h + 1] - m);
                s += e[2 * nt] + e[2 * nt + 1];
            }
            s += __shfl_xor_sync(FULL, s, 1);
            s += __shfl_xor_sync(FULL, s, 2);
            float inv = 1.f / s;
            int row = m0 + g + 8 * h;
#pragma unroll
            for (int nt = 0; nt < 8; nt++) {
                uint2 pr = split_pair(e[2 * nt] * inv, e[2 * nt + 1] * inv);
                DH[row * STR + 4 * nt + tq] = pr.x;
                DL[row * STR + 4 * nt + tq] = pr.y;
            }
        }
    }
    __syncthreads();

    // ---- P4: out = A1@V + A2@Qn; epilogue packs O pairs-along-c via shfl -> OC ----
    {
        const int m0 = (wid & 3) * 16;
        const int n0 = (wid >> 2) * 32;
        const int ntb = (wid >> 2) * 4;   // global n-tile base
        float acc[4][4];
#pragma unroll
        for (int i = 0; i < 4; i++)
#pragma unroll
            for (int j = 0; j < 4; j++) acc[i][j] = 0.f;
        const unsigned a1h0 = sptr(A1H), a1l0 = sptr(A1L);
        const unsigned a2h0 = sptr(A2H), a2l0 = sptr(A2L);
        const unsigned vh0 = sptr(VH), vl0 = sptr(VL);
        const unsigned aoffb = (m0 + rhA * 8 + rr) * 144 + bA * 16;
#pragma unroll
        for (int s = 0; s < 4; s++) {
            unsigned a1h[4], a1l[4], a2h[4], a2l[4];
            ldsm4(a1h, a1h0 + aoffb + s * 32);
            ldsm4(a1l, a1l0 + aoffb + s * 32);
            ldsm4(a2h, a2h0 + aoffb + s * 32);
            ldsm4(a2l, a2l0 + aoffb + s * 32);
#pragma unroll
            for (int np = 0; np < 2; np++) {
                // out1 B: V^T via ldmatrix.trans (rows = k = channel, cols = p)
                unsigned vo = (16 * s + bB * 8 + rr) * 144 + (n0 + (np * 2 + ntl) * 8) * 2;
                unsigned bhr[4], blr[4];
                ldsm4t(bhr, vh0 + vo);
                ldsm4t(blr, vl0 + vo);
                unsigned bh0[2] = {bhr[0], bhr[1]}, bl0[2] = {blr[0], blr[1]};
                unsigned bh1[2] = {bhr[2], bhr[3]}, bl1[2] = {blr[2], blr[3]};
                mma3(acc[np * 2],     a1h, a1l, bh0, bl0);
                mma3(acc[np * 2 + 1], a1h, a1l, bh1, bl1);
                // out2 B: qn c-packed from gmem (fragment record)
#pragma unroll
                for (int half = 0; half < 2; half++) {
                    int nt = np * 2 + half;
                    uint4 Q = __ldg(&qcb[(((ntb + nt) * 4 + s) * 8 + g) * 4 + tq]);
                    unsigned bh[2] = {Q.x, Q.z}, bl[2] = {Q.y, Q.w};
                    mma3(acc[nt], a2h, a2l, bh, bl);
                }
            }
        }
        // Epilogue: pair adjacent-c rows across lanes (lane^4 = g parity) and
        // store packed OC[p][cw] directly (OC overlays dead KN region).
        const bool evn = ((g & 1) == 0);
#pragma unroll
        for (int nt = 0; nt < 4; nt++) {
            float pv0 = __shfl_xor_sync(FULL, acc[nt][0], 4);
            float pv1 = __shfl_xor_sync(FULL, acc[nt][1], 4);
            float pv2 = __shfl_xor_sync(FULL, acc[nt][2], 4);
            float pv3 = __shfl_xor_sync(FULL, acc[nt][3], 4);
            int c = n0 + 8 * nt + 2 * tq;
            uint2 w0, w1;
            int cw;
            if (evn) {
                w0 = split_pair(acc[nt][0], pv0);   // rows (m0+g, m0+g+1), col c
                w1 = split_pair(acc[nt][1], pv1);   // col c+1
                cw = (m0 + g) >> 1;
            } else {
                w0 = split_pair(pv2, acc[nt][2]);   // rows (m0+g+7, m0+g+8), col c
                w1 = split_pair(pv3, acc[nt][3]);   // col c+1
                cw = (m0 + g + 7) >> 1;
            }
            OCH[c * STR + cw] = w0.x;
            OCL[c * STR + cw] = w0.y;
            OCH[(c + 1) * STR + cw] = w1.x;
            OCL[(c + 1) * STR + cw] = w1.y;
        }
    }
    __syncthreads();

    // ---- P6: proj y = PW @ O -> gmem (roll +4), float2 stores ----
    {
        const int m0 = (wid & 3) * 16;
        const int n0 = (wid >> 2) * 32;
        float acc[4][4];
#pragma unroll
        for (int i = 0; i < 4; i++)
#pragma unroll
            for (int j = 0; j < 4; j++) acc[i][j] = 0.f;
        const unsigned och0 = sptr(OCH), ocl0 = sptr(OCL);
#pragma unroll
        for (int s = 0; s < 4; s++) {
            int recA = ((((wid & 3) * 4 + s) * 8 + g) * 4 + tq) * 2;
            uint4 A0 = __ldg(&g_pwf[recA]);
            uint4 A1v = __ldg(&g_pwf[recA + 1]);
            unsigned ah[4] = {A0.x, A0.z, A1v.x, A1v.z};
            unsigned al[4] = {A0.y, A0.w, A1v.y, A1v.w};
#pragma unroll
            for (int np = 0; np < 2; np++) {
                unsigned ro = (n0 + (np * 2 + ntl) * 8 + rr) * 144 + bB * 16 + s * 32;
                unsigned bhr[4], blr[4];
                ldsm4(bhr, och0 + ro);
                ldsm4(blr, ocl0 + ro);
                unsigned bh0[2] = {bhr[0], bhr[1]}, bl0[2] = {blr[0], blr[1]};
                unsigned bh1[2] = {bhr[2], bhr[3]}, bl1[2] = {blr[2], blr[3]};
                mma3(acc[np * 2],     ah, al, bh0, bl0);
                mma3(acc[np * 2 + 1], ah, al, bh1, bl1);
            }
        }
        float* ob = out + (size_t)b * 64 * HH * WW_;
#pragma unroll
        for (int nt = 0; nt < 4; nt++) {
            int c = n0 + 8 * nt + 2 * tq;
            int pi = c >> 3;                        // pj = 2tq (pair stays in-row)
            int gh = (wh * 8 + pi + SHIFT) & 255;
            int gw = (ww * 8 + (c & 7) + SHIFT) & 255;
#pragma unroll
            for (int ri = 0; ri < 2; ri++) {
                int r = (m0 + g) + ri * 8;
                *(float2*)&ob[(size_t)r * HH * WW_ + (size_t)gh * WW_ + gw] =
                    make_float2(acc[nt][ri * 2], acc[nt][ri * 2 + 1]);
            }
        }
    }
}

extern "C" void kernel_launch(void* const* d_in, const int* in_sizes, int n_in,
                              void* d_out, int out_size) {
    const float* x      = (const float*)d_in[0];
    const float* q      = (const float*)d_in[1];
    const float* kv_w   = (const float*)d_in[2];
    const float* dw_w   = (const float*)d_in[3];
    const float* proj_w = (const float*)d_in[4];
    const float* rs1    = (const float*)d_in[5];
    const float* rs2    = (const float*)d_in[6];
    float* out = (float*)d_out;

    static bool attr_set = false;
    const int smem_bytes = 18432 * 4;  // 73,728 B
    if (!attr_set) {
        cudaFuncSetAttribute(win_kernel,
                             cudaFuncAttributeMaxDynamicSharedMemorySize,
                             smem_bytes);
        attr_set = true;
    }

    prep<<<32, 256>>>(q, kv_w, proj_w);
    win_kernel<<<8192, 256, smem_bytes>>>(x, dw_w, rs1, rs2, out);
}